// round 2
// baseline (speedup 1.0000x reference)
#include <cuda_runtime.h>
#include <cuda_bf16.h>
#include <mma.h>

using namespace nvcuda;

#define N_TOK 1024
#define DIM   2048
#define FDIM  5632
#define NEXP  8
#define RANK  16
#define LSCALE 2.0f

// ---------------- scratch (device globals; no allocations allowed) ----------------
__device__ float g_l1[N_TOK * 128];                 // x @ A1^T  [N, E*R]
__device__ float g_l3[N_TOK * 128];                 // x @ A3^T
__device__ float g_Y1[N_TOK * FDIM];                // x @ W1^T
__device__ float g_Y3[N_TOK * FDIM];                // x @ W3^T
__device__ float g_sbuf[2 * N_TOK * FDIM];          // s per (token, slot k)
__device__ float g_smix[N_TOK * FDIM];              // w0*s0 + w1*s1
__device__ float g_l2acc[2 * N_TOK * RANK];         // sum_f s * A2
__device__ float g_topw[2 * N_TOK];
__device__ int   g_topi[2 * N_TOK];
__device__ int   g_cnt[NEXP];
__device__ int   g_list[NEXP * N_TOK];              // codes (n<<1)|k grouped by expert

// ---------------- utility ----------------
__device__ __forceinline__ void cp16(float* smem_dst, const float* gsrc) {
    unsigned s = (unsigned)__cvta_generic_to_shared(smem_dst);
    asm volatile("cp.async.cg.shared.global [%0], [%1], 16;\n" :: "r"(s), "l"(gsrc));
}

// ---------------- zero scratch that is accumulated into ----------------
__global__ void zero_kernel() {
    int i = blockIdx.x * blockDim.x + threadIdx.x;
    if (i < 2 * N_TOK * RANK) g_l2acc[i] = 0.f;
    if (i < NEXP) g_cnt[i] = 0;
}

// ---------------- router: logits, top-2, renormalized weights ----------------
__global__ __launch_bounds__(256) void router_kernel(const float* __restrict__ x,
                                                     const float* __restrict__ gate,
                                                     float* __restrict__ logits_out) {
    int n = blockIdx.x;
    __shared__ float xs[DIM];
    __shared__ float lg[NEXP];
    for (int i = threadIdx.x; i < DIM; i += 256) xs[i] = x[(size_t)n * DIM + i];
    __syncthreads();
    int wid = threadIdx.x >> 5, lane = threadIdx.x & 31;
    const float* g = gate + (size_t)wid * DIM;   // warp wid handles expert wid
    float s = 0.f;
    for (int d = lane; d < DIM; d += 32) s += xs[d] * g[d];
    #pragma unroll
    for (int o = 16; o; o >>= 1) s += __shfl_xor_sync(0xffffffffu, s, o);
    if (lane == 0) lg[wid] = s;
    __syncthreads();
    if (threadIdx.x == 0) {
        #pragma unroll
        for (int e = 0; e < NEXP; e++) logits_out[n * NEXP + e] = lg[e];
        int i0 = 0; float v0 = lg[0];
        #pragma unroll
        for (int e = 1; e < NEXP; e++) if (lg[e] > v0) { v0 = lg[e]; i0 = e; }
        int i1 = -1; float v1 = -1e30f;
        #pragma unroll
        for (int e = 0; e < NEXP; e++) if (e != i0 && lg[e] > v1) { v1 = lg[e]; i1 = e; }
        float w0 = 1.f / (1.f + expf(v1 - v0));   // = p0/(p0+p1), renormalized
        g_topi[2 * n] = i0; g_topi[2 * n + 1] = i1;
        g_topw[2 * n] = w0; g_topw[2 * n + 1] = 1.f - w0;
    }
}

// ---------------- group (token, slot) pairs by expert ----------------
__global__ void build_lists_kernel() {
    int n = blockIdx.x * blockDim.x + threadIdx.x;
    if (n >= N_TOK) return;
    #pragma unroll
    for (int k = 0; k < 2; k++) {
        int e = g_topi[2 * n + k];
        int p = atomicAdd(&g_cnt[e], 1);
        g_list[e * N_TOK + p] = (n << 1) | k;
    }
}

// ---------------- tf32 wmma GEMM: C[M,Ncols] = A[M,K] * B[Ncols,K]^T ----------------
#define GBM 128
#define GBN 128
#define GBK 32
#define GLD (GBK + 4)   // 36 floats/row -> 144B, 16B-aligned rows

__global__ __launch_bounds__(256) void gemm_tn_kernel(const float* __restrict__ A,
                                                      const float* __restrict__ B,
                                                      float* __restrict__ C,
                                                      int M, int Ncols, int K) {
    extern __shared__ __align__(16) float sm[];
    float* As = sm;                       // [2][GBM*GLD]
    float* Bs = sm + 2 * GBM * GLD;       // [2][GBN*GLD]
    int bm = blockIdx.y, bn = blockIdx.x;
    const float* Ag = A + (size_t)bm * GBM * K;
    const float* Bg = B + (size_t)bn * GBN * K;
    int tid = threadIdx.x;
    int lrow = tid >> 3;
    int lcol = (tid & 7) * 4;
    int nk = K / GBK;

    // prologue: stage tile 0
    {
        #pragma unroll
        for (int i = 0; i < 4; i++) {
            int r = lrow + i * 32;
            cp16(&As[r * GLD + lcol], Ag + (size_t)r * K + lcol);
            cp16(&Bs[r * GLD + lcol], Bg + (size_t)r * K + lcol);
        }
        asm volatile("cp.async.commit_group;\n");
    }

    int wid = tid >> 5;
    int wm = wid >> 2, wn = wid & 3;      // 2x4 warp grid; warp tile 64x32
    wmma::fragment<wmma::accumulator, 16, 16, 8, float> acc[4][2];
    #pragma unroll
    for (int i = 0; i < 4; i++)
        #pragma unroll
        for (int j = 0; j < 2; j++) wmma::fill_fragment(acc[i][j], 0.f);

    for (int kt = 0; kt < nk; kt++) {
        int buf = kt & 1;
        if (kt + 1 < nk) {
            int nb = (kt + 1) & 1;
            const float* a = Ag + (size_t)(kt + 1) * GBK;
            const float* b = Bg + (size_t)(kt + 1) * GBK;
            #pragma unroll
            for (int i = 0; i < 4; i++) {
                int r = lrow + i * 32;
                cp16(&As[nb * GBM * GLD + r * GLD + lcol], a + (size_t)r * K + lcol);
                cp16(&Bs[nb * GBN * GLD + r * GLD + lcol], b + (size_t)r * K + lcol);
            }
            asm volatile("cp.async.commit_group;\n");
            asm volatile("cp.async.wait_group 1;\n");
        } else {
            asm volatile("cp.async.wait_group 0;\n");
        }
        __syncthreads();
        const float* Ab = As + buf * GBM * GLD;
        const float* Bb = Bs + buf * GBN * GLD;
        #pragma unroll
        for (int kk = 0; kk < GBK; kk += 8) {
            wmma::fragment<wmma::matrix_a, 16, 16, 8, wmma::precision::tf32, wmma::row_major> af[4];
            wmma::fragment<wmma::matrix_b, 16, 16, 8, wmma::precision::tf32, wmma::col_major> bf[2];
            #pragma unroll
            for (int i = 0; i < 4; i++) {
                wmma::load_matrix_sync(af[i], Ab + (wm * 64 + i * 16) * GLD + kk, GLD);
                #pragma unroll
                for (int t = 0; t < af[i].num_elements; t++)
                    af[i].x[t] = wmma::__float_to_tf32(af[i].x[t]);
            }
            #pragma unroll
            for (int j = 0; j < 2; j++) {
                wmma::load_matrix_sync(bf[j], Bb + (wn * 32 + j * 16) * GLD + kk, GLD);
                #pragma unroll
                for (int t = 0; t < bf[j].num_elements; t++)
                    bf[j].x[t] = wmma::__float_to_tf32(bf[j].x[t]);
            }
            #pragma unroll
            for (int i = 0; i < 4; i++)
                #pragma unroll
                for (int j = 0; j < 2; j++)
                    wmma::mma_sync(acc[i][j], af[i], bf[j], acc[i][j]);
        }
        __syncthreads();
    }
    #pragma unroll
    for (int i = 0; i < 4; i++)
        #pragma unroll
        for (int j = 0; j < 2; j++)
            wmma::store_matrix_sync(
                C + (size_t)(bm * GBM + wm * 64 + i * 16) * Ncols + bn * GBN + wn * 32 + j * 16,
                acc[i][j], Ncols, wmma::mem_row_major);
}

// ---------------- fused LoRA-B + SwiGLU per active (token, expert) ----------------
__global__ __launch_bounds__(128) void expert_kernel(const float* __restrict__ B1,
                                                     const float* __restrict__ B3) {
    int e = blockIdx.y;
    int f0 = blockIdx.x * 128;
    int f = threadIdx.x;
    __shared__ float B1s[16][128];
    __shared__ float B3s[16][128];
    __shared__ float lv[8][32];
    __shared__ int scode[8];

    {
        const float4* p1 = (const float4*)(B1 + (size_t)(e * FDIM + f0 + f) * RANK);
        const float4* p3 = (const float4*)(B3 + (size_t)(e * FDIM + f0 + f) * RANK);
        #pragma unroll
        for (int q = 0; q < 4; q++) {
            float4 v = p1[q];
            B1s[q * 4 + 0][f] = v.x; B1s[q * 4 + 1][f] = v.y;
            B1s[q * 4 + 2][f] = v.z; B1s[q * 4 + 3][f] = v.w;
            float4 u = p3[q];
            B3s[q * 4 + 0][f] = u.x; B3s[q * 4 + 1][f] = u.y;
            B3s[q * 4 + 2][f] = u.z; B3s[q * 4 + 3][f] = u.w;
        }
    }
    int cnt = g_cnt[e];
    for (int t0 = 0; t0 < cnt; t0 += 8) {
        int nt = (cnt - t0 < 8) ? (cnt - t0) : 8;
        __syncthreads();   // protects B-tiles (first iter) and lv reuse
        for (int idx = threadIdx.x; idx < nt * 32; idx += 128) {
            int ti = idx >> 5, r = idx & 31;
            int code = g_list[e * N_TOK + t0 + ti];
            int n = code >> 1;
            lv[ti][r] = (r < 16) ? g_l1[n * 128 + e * 16 + r]
                                 : g_l3[n * 128 + e * 16 + (r - 16)];
            if (r == 0) scode[ti] = code;
        }
        __syncthreads();
        for (int ti = 0; ti < nt; ti++) {
            int code = scode[ti];
            int n = code >> 1, k = code & 1;
            float b1 = g_Y1[(size_t)n * FDIM + f0 + f];
            float b3 = g_Y3[(size_t)n * FDIM + f0 + f];
            float h1 = 0.f, h3 = 0.f;
            #pragma unroll
            for (int r = 0; r < 16; r++) {
                h1 += lv[ti][r]      * B1s[r][f];
                h3 += lv[ti][16 + r] * B3s[r][f];
            }
            h1 = b1 + LSCALE * h1;
            h3 = b3 + LSCALE * h3;
            float sg = 1.f / (1.f + __expf(-h1));
            g_sbuf[(size_t)(2 * n + k) * FDIM + f0 + f] = h1 * sg * h3;
        }
    }
}

// ---------------- s_mix = w0*s0 + w1*s1 ----------------
__global__ void mix_kernel() {
    int idx = blockIdx.x * blockDim.x + threadIdx.x;
    if (idx >= N_TOK * FDIM) return;
    int n = idx / FDIM;
    int f = idx - n * FDIM;
    float w0 = g_topw[2 * n], w1 = g_topw[2 * n + 1];
    g_smix[idx] = w0 * g_sbuf[(size_t)(2 * n) * FDIM + f]
                + w1 * g_sbuf[(size_t)(2 * n + 1) * FDIM + f];
}

// ---------------- l2acc[n,k,r] = sum_f s * A2[e,r,f] (expert-grouped) ----------------
__global__ __launch_bounds__(128) void l2_kernel(const float* __restrict__ A2) {
    int e = blockIdx.y;
    int f0 = blockIdx.x * 512;
    __shared__ float A2s[16][516];   // padded: conflict-free across rr
    __shared__ float ss[512];
    for (int r = 0; r < 16; r++)
        for (int c = threadIdx.x; c < 512; c += 128)
            A2s[r][c] = A2[(size_t)(e * 16 + r) * FDIM + f0 + c];
    int rr = threadIdx.x >> 3, jj = threadIdx.x & 7;
    int cnt = g_cnt[e];
    for (int ti = 0; ti < cnt; ti++) {
        int code = g_list[e * N_TOK + ti];   // code == 2n+k
        __syncthreads();
        for (int c = threadIdx.x; c < 512; c += 128)
            ss[c] = g_sbuf[(size_t)code * FDIM + f0 + c];
        __syncthreads();
        float acc = 0.f;
        #pragma unroll 8
        for (int t = 0; t < 64; t++) {
            int c = t * 8 + jj;
            acc += ss[c] * A2s[rr][c];
        }
        acc += __shfl_xor_sync(0xffffffffu, acc, 1);
        acc += __shfl_xor_sync(0xffffffffu, acc, 2);
        acc += __shfl_xor_sync(0xffffffffu, acc, 4);
        if (jj == 0) atomicAdd(&g_l2acc[code * 16 + rr], acc);
    }
}

// ---------------- out += sum_k 2*w_k * (l2acc[n,k,:] . B2[e_k,d,:]) ----------------
__global__ __launch_bounds__(256) void final_kernel(const float* __restrict__ B2,
                                                    float* __restrict__ out) {
    int n = blockIdx.y;
    int d = blockIdx.x * 256 + threadIdx.x;
    __shared__ float lw[32];
    __shared__ int se[2];
    if (threadIdx.x < 32) {
        int k = threadIdx.x >> 4;
        lw[threadIdx.x] = g_l2acc[n * 32 + threadIdx.x] * (LSCALE * g_topw[2 * n + k]);
        if (threadIdx.x < 2) se[threadIdx.x] = g_topi[2 * n + threadIdx.x];
    }
    __syncthreads();
    float o = out[(size_t)n * DIM + d];
    #pragma unroll
    for (int k = 0; k < 2; k++) {
        const float4* b2 = (const float4*)(B2 + (size_t)(se[k] * DIM + d) * RANK);
        float a = 0.f;
        #pragma unroll
        for (int q = 0; q < 4; q++) {
            float4 v = b2[q];
            a += lw[k * 16 + q * 4 + 0] * v.x + lw[k * 16 + q * 4 + 1] * v.y
               + lw[k * 16 + q * 4 + 2] * v.z + lw[k * 16 + q * 4 + 3] * v.w;
        }
        o += a;
    }
    out[(size_t)n * DIM + d] = o;
}

// ---------------- host ----------------
extern "C" void kernel_launch(void* const* d_in, const int* in_sizes, int n_in,
                              void* d_out, int out_size) {
    const float* x    = (const float*)d_in[0];
    const float* gate = (const float*)d_in[1];
    const float* W1   = (const float*)d_in[2];
    const float* W3   = (const float*)d_in[3];
    const float* W2   = (const float*)d_in[4];
    const float* A1   = (const float*)d_in[5];
    const float* B1   = (const float*)d_in[6];
    const float* A3   = (const float*)d_in[7];
    const float* B3   = (const float*)d_in[8];
    const float* A2   = (const float*)d_in[9];
    const float* B2   = (const float*)d_in[10];
    float* out = (float*)d_out;
    float* logits = out + (size_t)N_TOK * DIM;   // output order: (out, logits)

    float *p_l1, *p_l3, *p_Y1, *p_Y3, *p_smix;
    cudaGetSymbolAddress((void**)&p_l1,   g_l1);
    cudaGetSymbolAddress((void**)&p_l3,   g_l3);
    cudaGetSymbolAddress((void**)&p_Y1,   g_Y1);
    cudaGetSymbolAddress((void**)&p_Y3,   g_Y3);
    cudaGetSymbolAddress((void**)&p_smix, g_smix);

    const int smem = (2 * GBM * GLD + 2 * GBN * GLD) * 4;   // 73728 B
    cudaFuncSetAttribute(gemm_tn_kernel, cudaFuncAttributeMaxDynamicSharedMemorySize, smem);

    zero_kernel<<<128, 256>>>();
    router_kernel<<<N_TOK, 256>>>(x, gate, logits);
    build_lists_kernel<<<4, 256>>>();

    // LoRA-A projections: [N,128] = x @ A{1,3}^T   (A is [E*R, D] row-major)
    gemm_tn_kernel<<<dim3(1, N_TOK / GBM), 256, smem>>>(x, A1, p_l1, N_TOK, 128, DIM);
    gemm_tn_kernel<<<dim3(1, N_TOK / GBM), 256, smem>>>(x, A3, p_l3, N_TOK, 128, DIM);
    // Base up-projections
    gemm_tn_kernel<<<dim3(FDIM / GBN, N_TOK / GBM), 256, smem>>>(x, W1, p_Y1, N_TOK, FDIM, DIM);
    gemm_tn_kernel<<<dim3(FDIM / GBN, N_TOK / GBM), 256, smem>>>(x, W3, p_Y3, N_TOK, FDIM, DIM);

    expert_kernel<<<dim3(FDIM / 128, NEXP), 128>>>(B1, B3);
    mix_kernel<<<(N_TOK * FDIM + 255) / 256, 256>>>();
    l2_kernel<<<dim3(FDIM / 512, NEXP), 128>>>(A2);

    // Down projection straight into d_out
    gemm_tn_kernel<<<dim3(DIM / GBN, N_TOK / GBM), 256, smem>>>(p_smix, W2, out, N_TOK, DIM, FDIM);
    final_kernel<<<dim3(DIM / 256, N_TOK), 256>>>(B2, out);
}

// round 4
// speedup vs baseline: 1.2142x; 1.2142x over previous
#include <cuda_runtime.h>
#include <mma.h>

using namespace nvcuda;

#define N_TOK 1024
#define DIM   2048
#define FDIM  5632
#define NEXP  8
#define RANK  16
#define LSCALE 2.0f

// ---------------- scratch (device globals; no allocations allowed) ----------------
__device__ __align__(256) float g_W1r[FDIM * DIM];
__device__ __align__(256) float g_W3r[FDIM * DIM];
__device__ __align__(256) float g_W2r[DIM * FDIM];
__device__ __align__(256) float g_xr[N_TOK * DIM];
__device__ __align__(256) float g_A1r[128 * DIM];
__device__ __align__(256) float g_A3r[128 * DIM];
__device__ __align__(256) float g_l1[N_TOK * 128];
__device__ __align__(256) float g_l3[N_TOK * 128];
__device__ __align__(256) float g_Y1[N_TOK * FDIM];
__device__ __align__(256) float g_Y3[N_TOK * FDIM];
__device__ __align__(256) float g_sbuf[2 * N_TOK * FDIM];
__device__ __align__(256) float g_smix[N_TOK * FDIM];
__device__ __align__(256) float g_psum[2 * N_TOK * DIM];
__device__ __align__(256) float g_l2acc[2 * N_TOK * RANK];
__device__ __align__(256) float g_topw[2 * N_TOK];
__device__ int   g_topi[2 * N_TOK];
__device__ int   g_cnt[NEXP];
__device__ int   g_list[NEXP * N_TOK];

// ---------------- utility ----------------
__device__ __forceinline__ void cp16(float* smem_dst, const float* gsrc) {
    unsigned s = (unsigned)__cvta_generic_to_shared(smem_dst);
    asm volatile("cp.async.cg.shared.global [%0], [%1], 16;\n" :: "r"(s), "l"(gsrc));
}

// ---------------- tf32 pre-rounding ----------------
__global__ void round_tf32_kernel(const float4* __restrict__ src, float4* __restrict__ dst, int n4) {
    int i = blockIdx.x * blockDim.x + threadIdx.x;
    if (i >= n4) return;
    float4 v = src[i], o;
    asm("cvt.rna.tf32.f32 %0, %1;" : "=f"(o.x) : "f"(v.x));
    asm("cvt.rna.tf32.f32 %0, %1;" : "=f"(o.y) : "f"(v.y));
    asm("cvt.rna.tf32.f32 %0, %1;" : "=f"(o.z) : "f"(v.z));
    asm("cvt.rna.tf32.f32 %0, %1;" : "=f"(o.w) : "f"(v.w));
    dst[i] = o;
}

__global__ void zero_kernel() {
    int i = blockIdx.x * blockDim.x + threadIdx.x;
    if (i < 2 * N_TOK * RANK) g_l2acc[i] = 0.f;
    if (i < NEXP) g_cnt[i] = 0;
}

// ---------------- router ----------------
__global__ __launch_bounds__(256) void router_kernel(const float* __restrict__ x,
                                                     const float* __restrict__ gate,
                                                     float* __restrict__ logits_out) {
    int n = blockIdx.x;
    __shared__ float xs[DIM];
    __shared__ float lg[NEXP];
    for (int i = threadIdx.x; i < DIM; i += 256) xs[i] = x[(size_t)n * DIM + i];
    __syncthreads();
    int wid = threadIdx.x >> 5, lane = threadIdx.x & 31;
    const float* g = gate + (size_t)wid * DIM;
    float s = 0.f;
    for (int d = lane; d < DIM; d += 32) s += xs[d] * g[d];
    #pragma unroll
    for (int o = 16; o; o >>= 1) s += __shfl_xor_sync(0xffffffffu, s, o);
    if (lane == 0) lg[wid] = s;
    __syncthreads();
    if (threadIdx.x == 0) {
        #pragma unroll
        for (int e = 0; e < NEXP; e++) logits_out[n * NEXP + e] = lg[e];
        int i0 = 0; float v0 = lg[0];
        #pragma unroll
        for (int e = 1; e < NEXP; e++) if (lg[e] > v0) { v0 = lg[e]; i0 = e; }
        int i1 = -1; float v1 = -1e30f;
        #pragma unroll
        for (int e = 0; e < NEXP; e++) if (e != i0 && lg[e] > v1) { v1 = lg[e]; i1 = e; }
        float w0 = 1.f / (1.f + expf(v1 - v0));
        g_topi[2 * n] = i0; g_topi[2 * n + 1] = i1;
        g_topw[2 * n] = w0; g_topw[2 * n + 1] = 1.f - w0;
    }
}

__global__ void build_lists_kernel() {
    int n = blockIdx.x * blockDim.x + threadIdx.x;
    if (n >= N_TOK) return;
    #pragma unroll
    for (int k = 0; k < 2; k++) {
        int e = g_topi[2 * n + k];
        int p = atomicAdd(&g_cnt[e], 1);
        g_list[e * N_TOK + p] = (n << 1) | k;
    }
}

// ---------------- tf32 mma GEMM: C[M,N] = A[M,K] * B[N,K]^T (pre-rounded inputs) ----
#define GBM 128
#define GBN 128
#define GBK 32
#define GLD 36                         // padded row: 36 floats = 144B
#define STG_F ((GBM + GBN) * GLD)      // floats per stage = 9216
#define GEMM_SMEM (3 * STG_F * 4)      // 110592 B

__device__ __forceinline__ void gemm_core(const float* __restrict__ Ag,
                                          const float* __restrict__ Bg,
                                          float* __restrict__ Cg,
                                          int Kstride, int Klen, int Cld) {
    extern __shared__ __align__(16) float sm[];
    int tid = threadIdx.x;
    int lrow = tid >> 3;               // 0..31
    int lcol = (tid & 7) * 4;          // 0..28
    int nkt = Klen / GBK;

    auto fill = [&](int kt, int slot) {
        float* As = sm + slot * STG_F;
        float* Bs = As + GBM * GLD;
        const float* a = Ag + (size_t)kt * GBK;
        const float* b = Bg + (size_t)kt * GBK;
        #pragma unroll
        for (int i = 0; i < 4; i++) {
            int r = lrow + i * 32;
            cp16(&As[r * GLD + lcol], a + (size_t)r * Kstride + lcol);
            cp16(&Bs[r * GLD + lcol], b + (size_t)r * Kstride + lcol);
        }
        asm volatile("cp.async.commit_group;\n" ::: "memory");
    };

    fill(0, 0);
    if (nkt > 1) fill(1, 1);

    int wid = tid >> 5;
    int wm = wid >> 2, wn = wid & 3;   // 2x4 warps; warp tile 64x32
    wmma::fragment<wmma::accumulator, 16, 16, 8, float> acc[4][2];
    #pragma unroll
    for (int i = 0; i < 4; i++)
        #pragma unroll
        for (int j = 0; j < 2; j++) wmma::fill_fragment(acc[i][j], 0.f);

    for (int kt = 0; kt < nkt; kt++) {
        if (nkt - kt >= 2) asm volatile("cp.async.wait_group 1;\n" ::: "memory");
        else               asm volatile("cp.async.wait_group 0;\n" ::: "memory");
        __syncthreads();
        if (kt + 2 < nkt) fill(kt + 2, (kt + 2) % 3);   // slot was freed last iter
        const float* Ab = sm + (kt % 3) * STG_F;
        const float* Bb = Ab + GBM * GLD;
        #pragma unroll
        for (int kk = 0; kk < GBK; kk += 8) {
            wmma::fragment<wmma::matrix_a, 16, 16, 8, wmma::precision::tf32, wmma::row_major> af[4];
            wmma::fragment<wmma::matrix_b, 16, 16, 8, wmma::precision::tf32, wmma::col_major> bf[2];
            #pragma unroll
            for (int i = 0; i < 4; i++)
                wmma::load_matrix_sync(af[i], Ab + (wm * 64 + i * 16) * GLD + kk, GLD);
            #pragma unroll
            for (int j = 0; j < 2; j++)
                wmma::load_matrix_sync(bf[j], Bb + (wn * 32 + j * 16) * GLD + kk, GLD);
            #pragma unroll
            for (int i = 0; i < 4; i++)
                #pragma unroll
                for (int j = 0; j < 2; j++)
                    wmma::mma_sync(acc[i][j], af[i], bf[j], acc[i][j]);
        }
        __syncthreads();
    }
    #pragma unroll
    for (int i = 0; i < 4; i++)
        #pragma unroll
        for (int j = 0; j < 2; j++)
            wmma::store_matrix_sync(
                Cg + (size_t)(wm * 64 + i * 16) * Cld + wn * 32 + j * 16,
                acc[i][j], Cld, wmma::mem_row_major);
}

// launch1: x @ {W1(44 tiles), W3(44), A1(1), A3(1)}^T.  grid (8, 90)
__global__ __launch_bounds__(256, 2) void gemm_fused1_kernel() {
    int bm = blockIdx.x, by = blockIdx.y;
    const float* Ag = g_xr + (size_t)bm * GBM * DIM;
    const float* Bg;
    float* Cg;
    int Cld;
    if (by < 44) {
        Bg = g_W1r + (size_t)by * GBN * DIM;
        Cg = g_Y1 + (size_t)bm * GBM * FDIM + by * GBN;
        Cld = FDIM;
    } else if (by < 88) {
        int b = by - 44;
        Bg = g_W3r + (size_t)b * GBN * DIM;
        Cg = g_Y3 + (size_t)bm * GBM * FDIM + b * GBN;
        Cld = FDIM;
    } else if (by == 88) {
        Bg = g_A1r;
        Cg = g_l1 + (size_t)bm * GBM * 128;
        Cld = 128;
    } else {
        Bg = g_A3r;
        Cg = g_l3 + (size_t)bm * GBM * 128;
        Cld = 128;
    }
    gemm_core(Ag, Bg, Cg, DIM, DIM, Cld);
}

// launch2: smix @ W2^T, split-K=2.  grid (16, 8, 2)
__global__ __launch_bounds__(256, 2) void gemm_w2_kernel() {
    int bn = blockIdx.x, bm = blockIdx.y, ks = blockIdx.z;
    const float* Ag = g_smix + (size_t)bm * GBM * FDIM + ks * 2816;
    const float* Bg = g_W2r + (size_t)bn * GBN * FDIM + ks * 2816;
    float* Cg = g_psum + (size_t)ks * N_TOK * DIM + (size_t)bm * GBM * DIM + bn * GBN;
    gemm_core(Ag, Bg, Cg, FDIM, 2816, DIM);
}

// ---------------- fused LoRA-B + SwiGLU ----------------
__global__ __launch_bounds__(128) void expert_kernel(const float* __restrict__ B1,
                                                     const float* __restrict__ B3) {
    int e = blockIdx.y;
    int f0 = blockIdx.x * 128;
    int f = threadIdx.x;
    __shared__ float B1s[16][128];
    __shared__ float B3s[16][128];
    __shared__ float lv[8][32];
    __shared__ int scode[8];
    {
        const float4* p1 = (const float4*)(B1 + (size_t)(e * FDIM + f0 + f) * RANK);
        const float4* p3 = (const float4*)(B3 + (size_t)(e * FDIM + f0 + f) * RANK);
        #pragma unroll
        for (int q = 0; q < 4; q++) {
            float4 v = p1[q];
            B1s[q * 4 + 0][f] = v.x; B1s[q * 4 + 1][f] = v.y;
            B1s[q * 4 + 2][f] = v.z; B1s[q * 4 + 3][f] = v.w;
            float4 u = p3[q];
            B3s[q * 4 + 0][f] = u.x; B3s[q * 4 + 1][f] = u.y;
            B3s[q * 4 + 2][f] = u.z; B3s[q * 4 + 3][f] = u.w;
        }
    }
    int cnt = g_cnt[e];
    for (int t0 = 0; t0 < cnt; t0 += 8) {
        int nt = (cnt - t0 < 8) ? (cnt - t0) : 8;
        __syncthreads();
        for (int idx = threadIdx.x; idx < nt * 32; idx += 128) {
            int ti = idx >> 5, r = idx & 31;
            int code = g_list[e * N_TOK + t0 + ti];
            int n = code >> 1;
            lv[ti][r] = (r < 16) ? g_l1[n * 128 + e * 16 + r]
                                 : g_l3[n * 128 + e * 16 + (r - 16)];
            if (r == 0) scode[ti] = code;
        }
        __syncthreads();
        for (int ti = 0; ti < nt; ti++) {
            int code = scode[ti];
            int n = code >> 1, k = code & 1;
            float b1 = g_Y1[(size_t)n * FDIM + f0 + f];
            float b3 = g_Y3[(size_t)n * FDIM + f0 + f];
            float h1 = 0.f, h3 = 0.f;
            #pragma unroll
            for (int r = 0; r < 16; r++) {
                h1 += lv[ti][r]      * B1s[r][f];
                h3 += lv[ti][16 + r] * B3s[r][f];
            }
            h1 = b1 + LSCALE * h1;
            h3 = b3 + LSCALE * h3;
            float sg = 1.f / (1.f + __expf(-h1));
            g_sbuf[(size_t)(2 * n + k) * FDIM + f0 + f] = h1 * sg * h3;
        }
    }
}

// ---------------- s_mix = w0*s0 + w1*s1 (tf32-rounded for the W2 GEMM) ----------------
__global__ void mix_kernel() {
    int idx = blockIdx.x * blockDim.x + threadIdx.x;
    if (idx >= N_TOK * FDIM) return;
    int n = idx / FDIM;
    int f = idx - n * FDIM;
    float w0 = g_topw[2 * n], w1 = g_topw[2 * n + 1];
    float v = w0 * g_sbuf[(size_t)(2 * n) * FDIM + f]
            + w1 * g_sbuf[(size_t)(2 * n + 1) * FDIM + f];
    float r;
    asm("cvt.rna.tf32.f32 %0, %1;" : "=f"(r) : "f"(v));
    g_smix[idx] = r;
}

// ---------------- l2acc[code,r] = sum_f s * A2[e,r,f] ----------------
__global__ __launch_bounds__(128) void l2_kernel(const float* __restrict__ A2) {
    int e = blockIdx.y;
    int f0 = blockIdx.x * 512;
    __shared__ float A2s[16][516];
    __shared__ float ss[512];
    for (int r = 0; r < 16; r++)
        for (int c = threadIdx.x; c < 512; c += 128)
            A2s[r][c] = A2[(size_t)(e * 16 + r) * FDIM + f0 + c];
    int rr = threadIdx.x >> 3, jj = threadIdx.x & 7;
    int cnt = g_cnt[e];
    for (int ti = 0; ti < cnt; ti++) {
        int code = g_list[e * N_TOK + ti];
        __syncthreads();
        for (int c = threadIdx.x; c < 512; c += 128)
            ss[c] = g_sbuf[(size_t)code * FDIM + f0 + c];
        __syncthreads();
        float acc = 0.f;
        #pragma unroll 8
        for (int t = 0; t < 64; t++) {
            int c = t * 8 + jj;
            acc += ss[c] * A2s[rr][c];
        }
        acc += __shfl_xor_sync(0xffffffffu, acc, 1);
        acc += __shfl_xor_sync(0xffffffffu, acc, 2);
        acc += __shfl_xor_sync(0xffffffffu, acc, 4);
        if (jj == 0) atomicAdd(&g_l2acc[code * 16 + rr], acc);
    }
}

// ---------------- out = psum0 + psum1 + sum_k LSCALE*w_k*(l2 . B2) ----------------
__global__ __launch_bounds__(256) void final_kernel(const float* __restrict__ B2,
                                                    float* __restrict__ out) {
    int n = blockIdx.y;
    int d = blockIdx.x * 256 + threadIdx.x;
    __shared__ float lw[32];
    __shared__ int se[2];
    if (threadIdx.x < 32) {
        int k = threadIdx.x >> 4;
        lw[threadIdx.x] = g_l2acc[n * 32 + threadIdx.x] * (LSCALE * g_topw[2 * n + k]);
        if (threadIdx.x < 2) se[threadIdx.x] = g_topi[2 * n + threadIdx.x];
    }
    __syncthreads();
    size_t id = (size_t)n * DIM + d;
    float o = g_psum[id] + g_psum[id + (size_t)N_TOK * DIM];
    #pragma unroll
    for (int k = 0; k < 2; k++) {
        const float4* b2 = (const float4*)(B2 + (size_t)(se[k] * DIM + d) * RANK);
        float a = 0.f;
        #pragma unroll
        for (int q = 0; q < 4; q++) {
            float4 v = b2[q];
            a += lw[k * 16 + q * 4 + 0] * v.x + lw[k * 16 + q * 4 + 1] * v.y
               + lw[k * 16 + q * 4 + 2] * v.z + lw[k * 16 + q * 4 + 3] * v.w;
        }
        o += a;
    }
    out[id] = o;
}

// ---------------- host ----------------
extern "C" void kernel_launch(void* const* d_in, const int* in_sizes, int n_in,
                              void* d_out, int out_size) {
    const float* x    = (const float*)d_in[0];
    const float* gate = (const float*)d_in[1];
    const float* W1   = (const float*)d_in[2];
    const float* W3   = (const float*)d_in[3];
    const float* W2   = (const float*)d_in[4];
    const float* A1   = (const float*)d_in[5];
    const float* B1   = (const float*)d_in[6];
    const float* A3   = (const float*)d_in[7];
    const float* B3   = (const float*)d_in[8];
    const float* A2   = (const float*)d_in[9];
    const float* B2   = (const float*)d_in[10];
    float* out = (float*)d_out;
    float* logits = out + (size_t)N_TOK * DIM;   // output order: (out, logits)

    float *p_W1r, *p_W3r, *p_W2r, *p_xr, *p_A1r, *p_A3r;
    cudaGetSymbolAddress((void**)&p_W1r, g_W1r);
    cudaGetSymbolAddress((void**)&p_W3r, g_W3r);
    cudaGetSymbolAddress((void**)&p_W2r, g_W2r);
    cudaGetSymbolAddress((void**)&p_xr,  g_xr);
    cudaGetSymbolAddress((void**)&p_A1r, g_A1r);
    cudaGetSymbolAddress((void**)&p_A3r, g_A3r);

    cudaFuncSetAttribute(gemm_fused1_kernel, cudaFuncAttributeMaxDynamicSharedMemorySize, GEMM_SMEM);
    cudaFuncSetAttribute(gemm_w2_kernel,     cudaFuncAttributeMaxDynamicSharedMemorySize, GEMM_SMEM);

    zero_kernel<<<128, 256>>>();
    router_kernel<<<N_TOK, 256>>>(x, gate, logits);
    build_lists_kernel<<<4, 256>>>();

    const int NW = FDIM * DIM / 4;
    round_tf32_kernel<<<(NW + 255) / 256, 256>>>((const float4*)W1, (float4*)p_W1r, NW);
    round_tf32_kernel<<<(NW + 255) / 256, 256>>>((const float4*)W3, (float4*)p_W3r, NW);
    round_tf32_kernel<<<(NW + 255) / 256, 256>>>((const float4*)W2, (float4*)p_W2r, NW);
    const int NX = N_TOK * DIM / 4;
    round_tf32_kernel<<<(NX + 255) / 256, 256>>>((const float4*)x, (float4*)p_xr, NX);
    const int NA = 128 * DIM / 4;
    round_tf32_kernel<<<(NA + 255) / 256, 256>>>((const float4*)A1, (float4*)p_A1r, NA);
    round_tf32_kernel<<<(NA + 255) / 256, 256>>>((const float4*)A3, (float4*)p_A3r, NA);

    gemm_fused1_kernel<<<dim3(8, 90), 256, GEMM_SMEM>>>();

    expert_kernel<<<dim3(FDIM / 128, NEXP), 128>>>(B1, B3);
    mix_kernel<<<(N_TOK * FDIM + 255) / 256, 256>>>();
    l2_kernel<<<dim3(FDIM / 512, NEXP), 128>>>(A2);

    gemm_w2_kernel<<<dim3(16, 8, 2), 256, GEMM_SMEM>>>();
    final_kernel<<<dim3(DIM / 256, N_TOK), 256>>>(B2, out);
}

// round 5
// speedup vs baseline: 1.6105x; 1.3264x over previous
#include <cuda_runtime.h>
#include <cstdint>

#define N_TOK 1024
#define DIM   2048
#define FDIM  5632
#define NEXP  8
#define RANK  16
#define LSCALE 2.0f

// ---------------- scratch (device globals; no allocations allowed) ----------------
__device__ __align__(256) float g_W1r[FDIM * DIM];
__device__ __align__(256) float g_W3r[FDIM * DIM];
__device__ __align__(256) float g_W2r[DIM * FDIM];
__device__ __align__(256) float g_xr[N_TOK * DIM];
__device__ __align__(256) float g_A1r[128 * DIM];
__device__ __align__(256) float g_A3r[128 * DIM];
__device__ __align__(256) float g_l1[N_TOK * 128];
__device__ __align__(256) float g_l3[N_TOK * 128];
__device__ __align__(256) float g_Y1[N_TOK * FDIM];
__device__ __align__(256) float g_Y3[N_TOK * FDIM];
__device__ __align__(256) float g_sbuf[2 * N_TOK * FDIM];
__device__ __align__(256) float g_smix[N_TOK * FDIM];
__device__ __align__(256) float g_psum[4 * N_TOK * DIM];
__device__ __align__(256) float g_l2acc[2 * N_TOK * RANK];
__device__ __align__(256) float g_topw[2 * N_TOK];
__device__ int   g_topi[2 * N_TOK];
__device__ int   g_cnt[NEXP];
__device__ int   g_list[NEXP * N_TOK];

// ---------------- utility ----------------
__device__ __forceinline__ void cp16(float* smem_dst, const float* gsrc) {
    unsigned s = (unsigned)__cvta_generic_to_shared(smem_dst);
    asm volatile("cp.async.cg.shared.global [%0], [%1], 16;\n" :: "r"(s), "l"(gsrc));
}

#define MMA_TF32(c, a, b) \
    asm volatile("mma.sync.aligned.m16n8k8.row.col.f32.tf32.tf32.f32 " \
        "{%0,%1,%2,%3}, {%4,%5,%6,%7}, {%8,%9}, {%0,%1,%2,%3};\n" \
        : "+f"((c)[0]), "+f"((c)[1]), "+f"((c)[2]), "+f"((c)[3]) \
        : "r"((a)[0]), "r"((a)[1]), "r"((a)[2]), "r"((a)[3]), "r"((b)[0]), "r"((b)[1]))

// ---------------- tf32 mma GEMM: CTA 128x256, warp 64x64, BK=32, 3-stage ----------
#define GBM 128
#define GBN 256
#define GBK 32
#define GLD 36                             // padded row: 36 floats = 144B
#define STG_F ((GBM + GBN) * GLD)          // 13824 floats per stage
#define GEMM_SMEM (3 * STG_F * 4)          // 165888 B

__device__ __forceinline__ void gemm_core(const float* __restrict__ Ag,
                                          const float* __restrict__ Bg0,
                                          const float* __restrict__ Bg1,
                                          float* __restrict__ Cg0,
                                          float* __restrict__ Cg1,
                                          int Cld, int Kstride, int Klen) {
    extern __shared__ __align__(16) float sm[];
    int tid = threadIdx.x;
    int wid = tid >> 5, lane = tid & 31;
    int wm = wid >> 2, wn = wid & 3;       // warp grid 2x4, warp tile 64x64
    int nkt = Klen / GBK;

    auto fill = [&](int kt, int slot) {
        float* st = sm + slot * STG_F;
        const float* acol = Ag + (size_t)kt * GBK;
        const float* b0col = Bg0 + (size_t)kt * GBK;
        const float* b1col = Bg1 + (size_t)kt * GBK;
        #pragma unroll
        for (int i = 0; i < 12; i++) {
            int id = i * 256 + tid;        // 16B chunk id, 0..3071
            int row = id >> 3, q = id & 7;
            const float* src;
            if (row < GBM)            src = acol + (size_t)row * Kstride + q * 4;
            else if (row < GBM + 128) src = b0col + (size_t)(row - GBM) * Kstride + q * 4;
            else                      src = b1col + (size_t)(row - GBM - 128) * Kstride + q * 4;
            cp16(&st[row * GLD + q * 4], src);
        }
        asm volatile("cp.async.commit_group;\n" ::: "memory");
    };

    fill(0, 0);
    if (nkt > 1) fill(1, 1);

    float c[4][8][4];
    #pragma unroll
    for (int mi = 0; mi < 4; mi++)
        #pragma unroll
        for (int ni = 0; ni < 8; ni++)
            #pragma unroll
            for (int q = 0; q < 4; q++) c[mi][ni][q] = 0.f;

    int g = lane >> 2, t = lane & 3;

    for (int kt = 0; kt < nkt; kt++) {
        if (nkt - kt >= 2) asm volatile("cp.async.wait_group 1;\n" ::: "memory");
        else               asm volatile("cp.async.wait_group 0;\n" ::: "memory");
        __syncthreads();
        if (kt + 2 < nkt) fill(kt + 2, (kt + 2) % 3);
        const float* As = sm + (kt % 3) * STG_F;
        const float* Bs = As + GBM * GLD;
        #pragma unroll
        for (int kk = 0; kk < GBK; kk += 8) {
            int krow = kk + t;
            unsigned a[4][4], b[8][2];
            #pragma unroll
            for (int mi = 0; mi < 4; mi++) {
                int r0 = wm * 64 + mi * 16 + g;
                a[mi][0] = __float_as_uint(As[r0 * GLD + krow]);
                a[mi][1] = __float_as_uint(As[(r0 + 8) * GLD + krow]);
                a[mi][2] = __float_as_uint(As[r0 * GLD + krow + 4]);
                a[mi][3] = __float_as_uint(As[(r0 + 8) * GLD + krow + 4]);
            }
            #pragma unroll
            for (int ni = 0; ni < 8; ni++) {
                int n0 = wn * 64 + ni * 8 + g;
                b[ni][0] = __float_as_uint(Bs[n0 * GLD + krow]);
                b[ni][1] = __float_as_uint(Bs[n0 * GLD + krow + 4]);
            }
            #pragma unroll
            for (int mi = 0; mi < 4; mi++)
                #pragma unroll
                for (int ni = 0; ni < 8; ni++)
                    MMA_TF32(c[mi][ni], a[mi], b[ni]);
        }
        __syncthreads();
    }

    // epilogue: warp wn covers cols wn*64..wn*64+63, entirely in one 128-col half
    float* base = (wn < 2) ? Cg0 : Cg1;
    int colOff = (wn * 64) & 127;
    #pragma unroll
    for (int mi = 0; mi < 4; mi++) {
        int r0 = wm * 64 + mi * 16 + g;
        #pragma unroll
        for (int ni = 0; ni < 8; ni++) {
            int cc = colOff + ni * 8 + 2 * t;
            float2 v0 = make_float2(c[mi][ni][0], c[mi][ni][1]);
            float2 v1 = make_float2(c[mi][ni][2], c[mi][ni][3]);
            *(float2*)(base + (size_t)r0 * Cld + cc) = v0;
            *(float2*)(base + (size_t)(r0 + 8) * Cld + cc) = v1;
        }
    }
}

// launch1: x @ {W1(22 tiles), W3(22), [A1;A3](1)}^T.  grid (8, 45)
__global__ __launch_bounds__(256, 1) void gemm_fused1_kernel() {
    int bm = blockIdx.x, by = blockIdx.y;
    const float* Ag = g_xr + (size_t)bm * GBM * DIM;
    const float *Bg0, *Bg1;
    float *Cg0, *Cg1;
    int Cld;
    if (by < 22) {
        Bg0 = g_W1r + (size_t)by * GBN * DIM;
        Bg1 = Bg0 + (size_t)128 * DIM;
        Cg0 = g_Y1 + (size_t)bm * GBM * FDIM + by * GBN;
        Cg1 = Cg0 + 128;
        Cld = FDIM;
    } else if (by < 44) {
        int b = by - 22;
        Bg0 = g_W3r + (size_t)b * GBN * DIM;
        Bg1 = Bg0 + (size_t)128 * DIM;
        Cg0 = g_Y3 + (size_t)bm * GBM * FDIM + b * GBN;
        Cg1 = Cg0 + 128;
        Cld = FDIM;
    } else {
        Bg0 = g_A1r;
        Bg1 = g_A3r;
        Cg0 = g_l1 + (size_t)bm * GBM * 128;
        Cg1 = g_l3 + (size_t)bm * GBM * 128;
        Cld = 128;
    }
    gemm_core(Ag, Bg0, Bg1, Cg0, Cg1, Cld, DIM, DIM);
}

// launch2: smix @ W2^T, split-K=4.  grid (8, 8, 4), K=1408 each
__global__ __launch_bounds__(256, 1) void gemm_w2_kernel() {
    int bm = blockIdx.x, bn = blockIdx.y, ks = blockIdx.z;
    const float* Ag = g_smix + (size_t)bm * GBM * FDIM + ks * 1408;
    const float* Bg0 = g_W2r + (size_t)bn * GBN * FDIM + ks * 1408;
    const float* Bg1 = Bg0 + (size_t)128 * FDIM;
    float* Cg0 = g_psum + (size_t)ks * N_TOK * DIM + (size_t)bm * GBM * DIM + bn * GBN;
    gemm_core(Ag, Bg0, Bg1, Cg0, Cg0 + 128, DIM, FDIM, 1408);
}

// ---------------- tf32 pre-rounding ----------------
__global__ void round_tf32_kernel(const float4* __restrict__ src, float4* __restrict__ dst, int n4) {
    int i = blockIdx.x * blockDim.x + threadIdx.x;
    if (i >= n4) return;
    float4 v = src[i], o;
    asm("cvt.rna.tf32.f32 %0, %1;" : "=f"(o.x) : "f"(v.x));
    asm("cvt.rna.tf32.f32 %0, %1;" : "=f"(o.y) : "f"(v.y));
    asm("cvt.rna.tf32.f32 %0, %1;" : "=f"(o.z) : "f"(v.z));
    asm("cvt.rna.tf32.f32 %0, %1;" : "=f"(o.w) : "f"(v.w));
    dst[i] = o;
}

__global__ void zero_kernel() {
    int i = blockIdx.x * blockDim.x + threadIdx.x;
    if (i < 2 * N_TOK * RANK) g_l2acc[i] = 0.f;
    if (i < NEXP) g_cnt[i] = 0;
}

// ---------------- router ----------------
__global__ __launch_bounds__(256) void router_kernel(const float* __restrict__ x,
                                                     const float* __restrict__ gate,
                                                     float* __restrict__ logits_out) {
    int n = blockIdx.x;
    __shared__ float xs[DIM];
    __shared__ float lg[NEXP];
    for (int i = threadIdx.x; i < DIM; i += 256) xs[i] = x[(size_t)n * DIM + i];
    __syncthreads();
    int wid = threadIdx.x >> 5, lane = threadIdx.x & 31;
    const float* g = gate + (size_t)wid * DIM;
    float s = 0.f;
    for (int d = lane; d < DIM; d += 32) s += xs[d] * g[d];
    #pragma unroll
    for (int o = 16; o; o >>= 1) s += __shfl_xor_sync(0xffffffffu, s, o);
    if (lane == 0) lg[wid] = s;
    __syncthreads();
    if (threadIdx.x == 0) {
        #pragma unroll
        for (int e = 0; e < NEXP; e++) logits_out[n * NEXP + e] = lg[e];
        int i0 = 0; float v0 = lg[0];
        #pragma unroll
        for (int e = 1; e < NEXP; e++) if (lg[e] > v0) { v0 = lg[e]; i0 = e; }
        int i1 = -1; float v1 = -1e30f;
        #pragma unroll
        for (int e = 0; e < NEXP; e++) if (e != i0 && lg[e] > v1) { v1 = lg[e]; i1 = e; }
        float w0 = 1.f / (1.f + expf(v1 - v0));
        g_topi[2 * n] = i0; g_topi[2 * n + 1] = i1;
        g_topw[2 * n] = w0; g_topw[2 * n + 1] = 1.f - w0;
    }
}

__global__ void build_lists_kernel() {
    int n = blockIdx.x * blockDim.x + threadIdx.x;
    if (n >= N_TOK) return;
    #pragma unroll
    for (int k = 0; k < 2; k++) {
        int e = g_topi[2 * n + k];
        int p = atomicAdd(&g_cnt[e], 1);
        g_list[e * N_TOK + p] = (n << 1) | k;
    }
}

// ---------------- fused LoRA-B + SwiGLU ----------------
__global__ __launch_bounds__(128) void expert_kernel(const float* __restrict__ B1,
                                                     const float* __restrict__ B3) {
    int e = blockIdx.y;
    int f0 = blockIdx.x * 128;
    int f = threadIdx.x;
    __shared__ float B1s[16][128];
    __shared__ float B3s[16][128];
    __shared__ float lv[8][32];
    __shared__ int scode[8];
    {
        const float4* p1 = (const float4*)(B1 + (size_t)(e * FDIM + f0 + f) * RANK);
        const float4* p3 = (const float4*)(B3 + (size_t)(e * FDIM + f0 + f) * RANK);
        #pragma unroll
        for (int q = 0; q < 4; q++) {
            float4 v = p1[q];
            B1s[q * 4 + 0][f] = v.x; B1s[q * 4 + 1][f] = v.y;
            B1s[q * 4 + 2][f] = v.z; B1s[q * 4 + 3][f] = v.w;
            float4 u = p3[q];
            B3s[q * 4 + 0][f] = u.x; B3s[q * 4 + 1][f] = u.y;
            B3s[q * 4 + 2][f] = u.z; B3s[q * 4 + 3][f] = u.w;
        }
    }
    int cnt = g_cnt[e];
    for (int t0 = 0; t0 < cnt; t0 += 8) {
        int nt = (cnt - t0 < 8) ? (cnt - t0) : 8;
        __syncthreads();
        for (int idx = threadIdx.x; idx < nt * 32; idx += 128) {
            int ti = idx >> 5, r = idx & 31;
            int code = g_list[e * N_TOK + t0 + ti];
            int n = code >> 1;
            lv[ti][r] = (r < 16) ? g_l1[n * 128 + e * 16 + r]
                                 : g_l3[n * 128 + e * 16 + (r - 16)];
            if (r == 0) scode[ti] = code;
        }
        __syncthreads();
        for (int ti = 0; ti < nt; ti++) {
            int code = scode[ti];
            int n = code >> 1, k = code & 1;
            float b1 = g_Y1[(size_t)n * FDIM + f0 + f];
            float b3 = g_Y3[(size_t)n * FDIM + f0 + f];
            float h1 = 0.f, h3 = 0.f;
            #pragma unroll
            for (int r = 0; r < 16; r++) {
                h1 += lv[ti][r]      * B1s[r][f];
                h3 += lv[ti][16 + r] * B3s[r][f];
            }
            h1 = b1 + LSCALE * h1;
            h3 = b3 + LSCALE * h3;
            float sg = 1.f / (1.f + __expf(-h1));
            g_sbuf[(size_t)(2 * n + k) * FDIM + f0 + f] = h1 * sg * h3;
        }
    }
}

// ---------------- s_mix = w0*s0 + w1*s1 (tf32-rounded for the W2 GEMM) ----------------
__global__ void mix_kernel() {
    int idx = blockIdx.x * blockDim.x + threadIdx.x;
    if (idx >= N_TOK * FDIM) return;
    int n = idx / FDIM;
    int f = idx - n * FDIM;
    float w0 = g_topw[2 * n], w1 = g_topw[2 * n + 1];
    float v = w0 * g_sbuf[(size_t)(2 * n) * FDIM + f]
            + w1 * g_sbuf[(size_t)(2 * n + 1) * FDIM + f];
    float r;
    asm("cvt.rna.tf32.f32 %0, %1;" : "=f"(r) : "f"(v));
    g_smix[idx] = r;
}

// ---------------- l2acc[code,r] = sum_f s * A2[e,r,f] ----------------
__global__ __launch_bounds__(128) void l2_kernel(const float* __restrict__ A2) {
    int e = blockIdx.y;
    int f0 = blockIdx.x * 512;
    __shared__ float A2s[16][516];
    __shared__ float ss[512];
    for (int r = 0; r < 16; r++)
        for (int c = threadIdx.x; c < 512; c += 128)
            A2s[r][c] = A2[(size_t)(e * 16 + r) * FDIM + f0 + c];
    int rr = threadIdx.x >> 3, jj = threadIdx.x & 7;
    int cnt = g_cnt[e];
    for (int ti = 0; ti < cnt; ti++) {
        int code = g_list[e * N_TOK + ti];
        __syncthreads();
        for (int c = threadIdx.x; c < 512; c += 128)
            ss[c] = g_sbuf[(size_t)code * FDIM + f0 + c];
        __syncthreads();
        float acc = 0.f;
        #pragma unroll 8
        for (int t = 0; t < 64; t++) {
            int c = t * 8 + jj;
            acc += ss[c] * A2s[rr][c];
        }
        acc += __shfl_xor_sync(0xffffffffu, acc, 1);
        acc += __shfl_xor_sync(0xffffffffu, acc, 2);
        acc += __shfl_xor_sync(0xffffffffu, acc, 4);
        if (jj == 0) atomicAdd(&g_l2acc[code * 16 + rr], acc);
    }
}

// ---------------- out = sum psum + sum_k LSCALE*w_k*(l2 . B2) ----------------
__global__ __launch_bounds__(256) void final_kernel(const float* __restrict__ B2,
                                                    float* __restrict__ out) {
    int n = blockIdx.y;
    int d = blockIdx.x * 256 + threadIdx.x;
    __shared__ float lw[32];
    __shared__ int se[2];
    if (threadIdx.x < 32) {
        int k = threadIdx.x >> 4;
        lw[threadIdx.x] = g_l2acc[n * 32 + threadIdx.x] * (LSCALE * g_topw[2 * n + k]);
        if (threadIdx.x < 2) se[threadIdx.x] = g_topi[2 * n + threadIdx.x];
    }
    __syncthreads();
    size_t id = (size_t)n * DIM + d;
    float o = g_psum[id] + g_psum[id + (size_t)N_TOK * DIM]
            + g_psum[id + 2 * (size_t)N_TOK * DIM] + g_psum[id + 3 * (size_t)N_TOK * DIM];
    #pragma unroll
    for (int k = 0; k < 2; k++) {
        const float4* b2 = (const float4*)(B2 + (size_t)(se[k] * DIM + d) * RANK);
        float a = 0.f;
        #pragma unroll
        for (int q = 0; q < 4; q++) {
            float4 v = b2[q];
            a += lw[k * 16 + q * 4 + 0] * v.x + lw[k * 16 + q * 4 + 1] * v.y
               + lw[k * 16 + q * 4 + 2] * v.z + lw[k * 16 + q * 4 + 3] * v.w;
        }
        o += a;
    }
    out[id] = o;
}

// ---------------- host ----------------
extern "C" void kernel_launch(void* const* d_in, const int* in_sizes, int n_in,
                              void* d_out, int out_size) {
    const float* x    = (const float*)d_in[0];
    const float* gate = (const float*)d_in[1];
    const float* W1   = (const float*)d_in[2];
    const float* W3   = (const float*)d_in[3];
    const float* W2   = (const float*)d_in[4];
    const float* A1   = (const float*)d_in[5];
    const float* B1   = (const float*)d_in[6];
    const float* A3   = (const float*)d_in[7];
    const float* B3   = (const float*)d_in[8];
    const float* A2   = (const float*)d_in[9];
    const float* B2   = (const float*)d_in[10];
    float* out = (float*)d_out;
    float* logits = out + (size_t)N_TOK * DIM;   // output order: (out, logits)

    float *p_W1r, *p_W3r, *p_W2r, *p_xr, *p_A1r, *p_A3r;
    cudaGetSymbolAddress((void**)&p_W1r, g_W1r);
    cudaGetSymbolAddress((void**)&p_W3r, g_W3r);
    cudaGetSymbolAddress((void**)&p_W2r, g_W2r);
    cudaGetSymbolAddress((void**)&p_xr,  g_xr);
    cudaGetSymbolAddress((void**)&p_A1r, g_A1r);
    cudaGetSymbolAddress((void**)&p_A3r, g_A3r);

    cudaFuncSetAttribute(gemm_fused1_kernel, cudaFuncAttributeMaxDynamicSharedMemorySize, GEMM_SMEM);
    cudaFuncSetAttribute(gemm_w2_kernel,     cudaFuncAttributeMaxDynamicSharedMemorySize, GEMM_SMEM);

    // launches 1-5: rounding needed by gemm_fused1; launch 6 = gemm_fused1 (ncu -s 5 -c 1)
    const int NW = FDIM * DIM / 4;
    round_tf32_kernel<<<(NW + 255) / 256, 256>>>((const float4*)W1, (float4*)p_W1r, NW);
    round_tf32_kernel<<<(NW + 255) / 256, 256>>>((const float4*)W3, (float4*)p_W3r, NW);
    const int NX = N_TOK * DIM / 4;
    round_tf32_kernel<<<(NX + 255) / 256, 256>>>((const float4*)x, (float4*)p_xr, NX);
    const int NA = 128 * DIM / 4;
    round_tf32_kernel<<<(NA + 255) / 256, 256>>>((const float4*)A1, (float4*)p_A1r, NA);
    round_tf32_kernel<<<(NA + 255) / 256, 256>>>((const float4*)A3, (float4*)p_A3r, NA);

    gemm_fused1_kernel<<<dim3(8, 45), 256, GEMM_SMEM>>>();

    round_tf32_kernel<<<(NW + 255) / 256, 256>>>((const float4*)W2, (float4*)p_W2r, NW);
    zero_kernel<<<128, 256>>>();
    router_kernel<<<N_TOK, 256>>>(x, gate, logits);
    build_lists_kernel<<<4, 256>>>();

    expert_kernel<<<dim3(FDIM / 128, NEXP), 128>>>(B1, B3);
    mix_kernel<<<(N_TOK * FDIM + 255) / 256, 256>>>();
    l2_kernel<<<dim3(FDIM / 512, NEXP), 128>>>(A2);

    gemm_w2_kernel<<<dim3(8, 8, 4), 256, GEMM_SMEM>>>();
    final_kernel<<<dim3(DIM / 256, N_TOK), 256>>>(B2, out);
}

// round 6
// speedup vs baseline: 2.9338x; 1.8217x over previous
#include <cuda_runtime.h>
#include <cuda_fp16.h>
#include <cstdint>

#define N_TOK 1024
#define DIM   2048
#define FDIM  5632
#define NEXP  8
#define RANK  16
#define LSCALE 2.0f

// ---------------- scratch (device globals; no allocations allowed) ----------------
__device__ __align__(256) __half g_W1h[FDIM * DIM];
__device__ __align__(256) __half g_W3h[FDIM * DIM];
__device__ __align__(256) __half g_W2h[DIM * FDIM];
__device__ __align__(256) __half g_xh[N_TOK * DIM];
__device__ __align__(256) __half g_A1h[128 * DIM];
__device__ __align__(256) __half g_A3h[128 * DIM];
__device__ __align__(256) __half g_smixh[N_TOK * FDIM];
__device__ __align__(256) float g_l1[N_TOK * 128];
__device__ __align__(256) float g_l3[N_TOK * 128];
__device__ __align__(256) float g_Y1[N_TOK * FDIM];
__device__ __align__(256) float g_Y3[N_TOK * FDIM];
__device__ __align__(256) float g_sbuf[2 * N_TOK * FDIM];
__device__ __align__(256) float g_psum[4 * N_TOK * DIM];
__device__ __align__(256) float g_l2acc[2 * N_TOK * RANK];
__device__ __align__(256) float g_topw[2 * N_TOK];
__device__ int   g_topi[2 * N_TOK];
__device__ int   g_cnt[NEXP];
__device__ int   g_list[NEXP * N_TOK];

// ---------------- utility ----------------
__device__ __forceinline__ void cp16(const __half* smem_dst, const __half* gsrc) {
    unsigned s = (unsigned)__cvta_generic_to_shared(smem_dst);
    asm volatile("cp.async.cg.shared.global [%0], [%1], 16;\n" :: "r"(s), "l"(gsrc));
}

#define MMA_F16(c, a, b) \
    asm volatile("mma.sync.aligned.m16n8k16.row.col.f32.f16.f16.f32 " \
        "{%0,%1,%2,%3}, {%4,%5,%6,%7}, {%8,%9}, {%0,%1,%2,%3};\n" \
        : "+f"((c)[0]), "+f"((c)[1]), "+f"((c)[2]), "+f"((c)[3]) \
        : "r"((a)[0]), "r"((a)[1]), "r"((a)[2]), "r"((a)[3]), "r"((b)[0]), "r"((b)[1]))

// ---------------- fp16 mma GEMM: CTA 128x256, warp 64x64, BK=64, 3-stage ----------
#define GBM 128
#define GBN 256
#define GBK 64
#define GLDH 72                              // padded row: 72 halves = 144B
#define STG_H ((GBM + GBN) * GLDH)           // 27648 halves per stage
#define GEMM_SMEM (3 * STG_H * 2)            // 165888 B

__device__ __forceinline__ void gemm_core(const __half* __restrict__ Ag,
                                          const __half* __restrict__ Bg0,
                                          const __half* __restrict__ Bg1,
                                          float* __restrict__ Cg0,
                                          float* __restrict__ Cg1,
                                          int Cld, int Kstride, int Klen) {
    extern __shared__ __align__(16) __half smh[];
    int tid = threadIdx.x;
    int wid = tid >> 5, lane = tid & 31;
    int wm = wid >> 2, wn = wid & 3;         // warp grid 2x4, warp tile 64x64
    int g = lane >> 2, t = lane & 3;
    int nkt = Klen / GBK;

    auto fill = [&](int kt, int slot) {
        __half* st = smh + slot * STG_H;
        const __half* acol = Ag + (size_t)kt * GBK;
        const __half* b0col = Bg0 + (size_t)kt * GBK;
        const __half* b1col = Bg1 + (size_t)kt * GBK;
        #pragma unroll
        for (int i = 0; i < 12; i++) {
            int id = i * 256 + tid;          // 16B chunk id, 0..3071
            int row = id >> 3, q = id & 7;
            const __half* src;
            if (row < GBM)            src = acol + (size_t)row * Kstride + q * 8;
            else if (row < GBM + 128) src = b0col + (size_t)(row - GBM) * Kstride + q * 8;
            else                      src = b1col + (size_t)(row - GBM - 128) * Kstride + q * 8;
            cp16(st + row * GLDH + q * 8, src);
        }
        asm volatile("cp.async.commit_group;\n" ::: "memory");
    };

    fill(0, 0);
    if (nkt > 1) fill(1, 1);

    float c[4][8][4];
    #pragma unroll
    for (int mi = 0; mi < 4; mi++)
        #pragma unroll
        for (int ni = 0; ni < 8; ni++)
            #pragma unroll
            for (int q = 0; q < 4; q++) c[mi][ni][q] = 0.f;

    for (int kt = 0; kt < nkt; kt++) {
        if (nkt - kt >= 2) asm volatile("cp.async.wait_group 1;\n" ::: "memory");
        else               asm volatile("cp.async.wait_group 0;\n" ::: "memory");
        __syncthreads();
        if (kt + 2 < nkt) fill(kt + 2, (kt + 2) % 3);
        const __half* As = smh + (kt % 3) * STG_H;
        const __half* Bs = As + GBM * GLDH;
        #pragma unroll
        for (int s = 0; s < 4; s++) {
            int k0 = s * 16 + 2 * t;
            unsigned a[4][4], b[8][2];
            #pragma unroll
            for (int mi = 0; mi < 4; mi++) {
                int r0 = wm * 64 + mi * 16 + g;
                a[mi][0] = *(const unsigned*)(As + r0 * GLDH + k0);
                a[mi][1] = *(const unsigned*)(As + (r0 + 8) * GLDH + k0);
                a[mi][2] = *(const unsigned*)(As + r0 * GLDH + k0 + 8);
                a[mi][3] = *(const unsigned*)(As + (r0 + 8) * GLDH + k0 + 8);
            }
            #pragma unroll
            for (int ni = 0; ni < 8; ni++) {
                int n0 = wn * 64 + ni * 8 + g;
                b[ni][0] = *(const unsigned*)(Bs + n0 * GLDH + k0);
                b[ni][1] = *(const unsigned*)(Bs + n0 * GLDH + k0 + 8);
            }
            #pragma unroll
            for (int mi = 0; mi < 4; mi++)
                #pragma unroll
                for (int ni = 0; ni < 8; ni++)
                    MMA_F16(c[mi][ni], a[mi], b[ni]);
        }
        __syncthreads();
    }

    // epilogue: warp wn covers cols wn*64..wn*64+63, entirely in one 128-col half
    float* base = (wn < 2) ? Cg0 : Cg1;
    int colOff = (wn * 64) & 127;
    #pragma unroll
    for (int mi = 0; mi < 4; mi++) {
        int r0 = wm * 64 + mi * 16 + g;
        #pragma unroll
        for (int ni = 0; ni < 8; ni++) {
            int cc = colOff + ni * 8 + 2 * t;
            *(float2*)(base + (size_t)r0 * Cld + cc) = make_float2(c[mi][ni][0], c[mi][ni][1]);
            *(float2*)(base + (size_t)(r0 + 8) * Cld + cc) = make_float2(c[mi][ni][2], c[mi][ni][3]);
        }
    }
}

// launch1: x @ {W1(22 tiles), W3(22), [A1;A3](1)}^T.  grid (8, 45)
__global__ __launch_bounds__(256, 1) void gemm_fused1_kernel() {
    int bm = blockIdx.x, by = blockIdx.y;
    const __half* Ag = g_xh + (size_t)bm * GBM * DIM;
    const __half *Bg0, *Bg1;
    float *Cg0, *Cg1;
    int Cld;
    if (by < 22) {
        Bg0 = g_W1h + (size_t)by * GBN * DIM;
        Bg1 = Bg0 + (size_t)128 * DIM;
        Cg0 = g_Y1 + (size_t)bm * GBM * FDIM + by * GBN;
        Cg1 = Cg0 + 128;
        Cld = FDIM;
    } else if (by < 44) {
        int b = by - 22;
        Bg0 = g_W3h + (size_t)b * GBN * DIM;
        Bg1 = Bg0 + (size_t)128 * DIM;
        Cg0 = g_Y3 + (size_t)bm * GBM * FDIM + b * GBN;
        Cg1 = Cg0 + 128;
        Cld = FDIM;
    } else {
        Bg0 = g_A1h;
        Bg1 = g_A3h;
        Cg0 = g_l1 + (size_t)bm * GBM * 128;
        Cg1 = g_l3 + (size_t)bm * GBM * 128;
        Cld = 128;
    }
    gemm_core(Ag, Bg0, Bg1, Cg0, Cg1, Cld, DIM, DIM);
}

// launch2: smix @ W2^T, split-K=4.  grid (8, 8, 4), K=1408 each
__global__ __launch_bounds__(256, 1) void gemm_w2_kernel() {
    int bm = blockIdx.x, bn = blockIdx.y, ks = blockIdx.z;
    const __half* Ag = g_smixh + (size_t)bm * GBM * FDIM + ks * 1408;
    const __half* Bg0 = g_W2h + (size_t)bn * GBN * FDIM + ks * 1408;
    const __half* Bg1 = Bg0 + (size_t)128 * FDIM;
    float* Cg0 = g_psum + (size_t)ks * N_TOK * DIM + (size_t)bm * GBM * DIM + bn * GBN;
    gemm_core(Ag, Bg0, Bg1, Cg0, Cg0 + 128, DIM, FDIM, 1408);
}

// ---------------- fp32 -> fp16 conversion ----------------
__global__ void to_half_kernel(const float4* __restrict__ src, __half* __restrict__ dst, int n4) {
    int i = blockIdx.x * blockDim.x + threadIdx.x;
    if (i >= n4) return;
    float4 v = src[i];
    __half2* d = (__half2*)(dst + (size_t)i * 4);
    d[0] = __floats2half2_rn(v.x, v.y);
    d[1] = __floats2half2_rn(v.z, v.w);
}

// combined A1+A3 conversion (keeps gemm_fused1 as the 5th launch for ncu)
__global__ void to_half_a13_kernel(const float4* __restrict__ a1, const float4* __restrict__ a3) {
    const int n4 = 128 * DIM / 4;
    int i = blockIdx.x * blockDim.x + threadIdx.x;
    if (i >= 2 * n4) return;
    const float4* s = (i < n4) ? a1 : (a3 - n4);
    __half* d = (i < n4) ? g_A1h : (g_A3h - (size_t)n4 * 4);
    float4 v = s[i];
    __half2* dd = (__half2*)(d + (size_t)i * 4);
    dd[0] = __floats2half2_rn(v.x, v.y);
    dd[1] = __floats2half2_rn(v.z, v.w);
}

__global__ void zero_kernel() {
    int i = blockIdx.x * blockDim.x + threadIdx.x;
    if (i < 2 * N_TOK * RANK) g_l2acc[i] = 0.f;
    if (i < NEXP) g_cnt[i] = 0;
}

// ---------------- router ----------------
__global__ __launch_bounds__(256) void router_kernel(const float* __restrict__ x,
                                                     const float* __restrict__ gate,
                                                     float* __restrict__ logits_out) {
    int n = blockIdx.x;
    __shared__ float xs[DIM];
    __shared__ float lg[NEXP];
    for (int i = threadIdx.x; i < DIM; i += 256) xs[i] = x[(size_t)n * DIM + i];
    __syncthreads();
    int wid = threadIdx.x >> 5, lane = threadIdx.x & 31;
    const float* g = gate + (size_t)wid * DIM;
    float s = 0.f;
    for (int d = lane; d < DIM; d += 32) s += xs[d] * g[d];
    #pragma unroll
    for (int o = 16; o; o >>= 1) s += __shfl_xor_sync(0xffffffffu, s, o);
    if (lane == 0) lg[wid] = s;
    __syncthreads();
    if (threadIdx.x == 0) {
        #pragma unroll
        for (int e = 0; e < NEXP; e++) logits_out[n * NEXP + e] = lg[e];
        int i0 = 0; float v0 = lg[0];
        #pragma unroll
        for (int e = 1; e < NEXP; e++) if (lg[e] > v0) { v0 = lg[e]; i0 = e; }
        int i1 = -1; float v1 = -1e30f;
        #pragma unroll
        for (int e = 0; e < NEXP; e++) if (e != i0 && lg[e] > v1) { v1 = lg[e]; i1 = e; }
        float w0 = 1.f / (1.f + expf(v1 - v0));
        g_topi[2 * n] = i0; g_topi[2 * n + 1] = i1;
        g_topw[2 * n] = w0; g_topw[2 * n + 1] = 1.f - w0;
    }
}

__global__ void build_lists_kernel() {
    int n = blockIdx.x * blockDim.x + threadIdx.x;
    if (n >= N_TOK) return;
    #pragma unroll
    for (int k = 0; k < 2; k++) {
        int e = g_topi[2 * n + k];
        int p = atomicAdd(&g_cnt[e], 1);
        g_list[e * N_TOK + p] = (n << 1) | k;
    }
}

// ---------------- fused LoRA-B + SwiGLU ----------------
__global__ __launch_bounds__(128) void expert_kernel(const float* __restrict__ B1,
                                                     const float* __restrict__ B3) {
    int e = blockIdx.y;
    int f0 = blockIdx.x * 128;
    int f = threadIdx.x;
    __shared__ float B1s[16][128];
    __shared__ float B3s[16][128];
    __shared__ float lv[8][32];
    __shared__ int scode[8];
    {
        const float4* p1 = (const float4*)(B1 + (size_t)(e * FDIM + f0 + f) * RANK);
        const float4* p3 = (const float4*)(B3 + (size_t)(e * FDIM + f0 + f) * RANK);
        #pragma unroll
        for (int q = 0; q < 4; q++) {
            float4 v = p1[q];
            B1s[q * 4 + 0][f] = v.x; B1s[q * 4 + 1][f] = v.y;
            B1s[q * 4 + 2][f] = v.z; B1s[q * 4 + 3][f] = v.w;
            float4 u = p3[q];
            B3s[q * 4 + 0][f] = u.x; B3s[q * 4 + 1][f] = u.y;
            B3s[q * 4 + 2][f] = u.z; B3s[q * 4 + 3][f] = u.w;
        }
    }
    int cnt = g_cnt[e];
    for (int t0 = 0; t0 < cnt; t0 += 8) {
        int nt = (cnt - t0 < 8) ? (cnt - t0) : 8;
        __syncthreads();
        for (int idx = threadIdx.x; idx < nt * 32; idx += 128) {
            int ti = idx >> 5, r = idx & 31;
            int code = g_list[e * N_TOK + t0 + ti];
            int n = code >> 1;
            lv[ti][r] = (r < 16) ? g_l1[n * 128 + e * 16 + r]
                                 : g_l3[n * 128 + e * 16 + (r - 16)];
            if (r == 0) scode[ti] = code;
        }
        __syncthreads();
        for (int ti = 0; ti < nt; ti++) {
            int code = scode[ti];
            int n = code >> 1, k = code & 1;
            float b1 = g_Y1[(size_t)n * FDIM + f0 + f];
            float b3 = g_Y3[(size_t)n * FDIM + f0 + f];
            float h1 = 0.f, h3 = 0.f;
            #pragma unroll
            for (int r = 0; r < 16; r++) {
                h1 += lv[ti][r]      * B1s[r][f];
                h3 += lv[ti][16 + r] * B3s[r][f];
            }
            h1 = b1 + LSCALE * h1;
            h3 = b3 + LSCALE * h3;
            float sg = 1.f / (1.f + __expf(-h1));
            g_sbuf[(size_t)(2 * n + k) * FDIM + f0 + f] = h1 * sg * h3;
        }
    }
}

// ---------------- s_mix = w0*s0 + w1*s1 -> fp16 for the W2 GEMM ----------------
__global__ void mix_kernel() {
    int idx = blockIdx.x * blockDim.x + threadIdx.x;
    if (idx >= N_TOK * FDIM) return;
    int n = idx / FDIM;
    int f = idx - n * FDIM;
    float w0 = g_topw[2 * n], w1 = g_topw[2 * n + 1];
    float v = w0 * g_sbuf[(size_t)(2 * n) * FDIM + f]
            + w1 * g_sbuf[(size_t)(2 * n + 1) * FDIM + f];
    g_smixh[idx] = __float2half_rn(v);
}

// ---------------- l2acc[code,r] = sum_f s * A2[e,r,f], token-sliced ----------------
__global__ __launch_bounds__(128) void l2_kernel(const float* __restrict__ A2) {
    int e = blockIdx.y;
    int f0 = blockIdx.x * 512;
    int zslice = blockIdx.z;                 // tokens ti = zslice, zslice+4, ...
    __shared__ float A2s[16][516];
    __shared__ float ss[512];
    for (int r = 0; r < 16; r++)
        for (int c = threadIdx.x; c < 512; c += 128)
            A2s[r][c] = A2[(size_t)(e * 16 + r) * FDIM + f0 + c];
    int rr = threadIdx.x >> 3, jj = threadIdx.x & 7;
    int cnt = g_cnt[e];
    for (int ti = zslice; ti < cnt; ti += 4) {
        int code = g_list[e * N_TOK + ti];
        __syncthreads();
        for (int c = threadIdx.x; c < 512; c += 128)
            ss[c] = g_sbuf[(size_t)code * FDIM + f0 + c];
        __syncthreads();
        float acc = 0.f;
        #pragma unroll 8
        for (int t = 0; t < 64; t++) {
            int c = t * 8 + jj;
            acc += ss[c] * A2s[rr][c];
        }
        acc += __shfl_xor_sync(0xffffffffu, acc, 1);
        acc += __shfl_xor_sync(0xffffffffu, acc, 2);
        acc += __shfl_xor_sync(0xffffffffu, acc, 4);
        if (jj == 0) atomicAdd(&g_l2acc[code * 16 + rr], acc);
    }
}

// ---------------- out = sum psum + sum_k LSCALE*w_k*(l2 . B2) ----------------
__global__ __launch_bounds__(256) void final_kernel(const float* __restrict__ B2,
                                                    float* __restrict__ out) {
    int n = blockIdx.y;
    int d = blockIdx.x * 256 + threadIdx.x;
    __shared__ float lw[32];
    __shared__ int se[2];
    if (threadIdx.x < 32) {
        int k = threadIdx.x >> 4;
        lw[threadIdx.x] = g_l2acc[n * 32 + threadIdx.x] * (LSCALE * g_topw[2 * n + k]);
        if (threadIdx.x < 2) se[threadIdx.x] = g_topi[2 * n + threadIdx.x];
    }
    __syncthreads();
    size_t id = (size_t)n * DIM + d;
    float o = g_psum[id] + g_psum[id + (size_t)N_TOK * DIM]
            + g_psum[id + 2 * (size_t)N_TOK * DIM] + g_psum[id + 3 * (size_t)N_TOK * DIM];
    #pragma unroll
    for (int k = 0; k < 2; k++) {
        const float4* b2 = (const float4*)(B2 + (size_t)(se[k] * DIM + d) * RANK);
        float a = 0.f;
        #pragma unroll
        for (int q = 0; q < 4; q++) {
            float4 v = b2[q];
            a += lw[k * 16 + q * 4 + 0] * v.x + lw[k * 16 + q * 4 + 1] * v.y
               + lw[k * 16 + q * 4 + 2] * v.z + lw[k * 16 + q * 4 + 3] * v.w;
        }
        o += a;
    }
    out[id] = o;
}

// ---------------- host ----------------
extern "C" void kernel_launch(void* const* d_in, const int* in_sizes, int n_in,
                              void* d_out, int out_size) {
    const float* x    = (const float*)d_in[0];
    const float* gate = (const float*)d_in[1];
    const float* W1   = (const float*)d_in[2];
    const float* W3   = (const float*)d_in[3];
    const float* W2   = (const float*)d_in[4];
    const float* A1   = (const float*)d_in[5];
    const float* B1   = (const float*)d_in[6];
    const float* A3   = (const float*)d_in[7];
    const float* B3   = (const float*)d_in[8];
    const float* A2   = (const float*)d_in[9];
    const float* B2   = (const float*)d_in[10];
    float* out = (float*)d_out;
    float* logits = out + (size_t)N_TOK * DIM;   // output order: (out, logits)

    __half *p_W1h, *p_W3h, *p_W2h, *p_xh;
    cudaGetSymbolAddress((void**)&p_W1h, g_W1h);
    cudaGetSymbolAddress((void**)&p_W3h, g_W3h);
    cudaGetSymbolAddress((void**)&p_W2h, g_W2h);
    cudaGetSymbolAddress((void**)&p_xh,  g_xh);

    cudaFuncSetAttribute(gemm_fused1_kernel, cudaFuncAttributeMaxDynamicSharedMemorySize, GEMM_SMEM);
    cudaFuncSetAttribute(gemm_w2_kernel,     cudaFuncAttributeMaxDynamicSharedMemorySize, GEMM_SMEM);

    // launches 1-4 feed gemm_fused1; launch 5 = gemm_fused1 (ncu -s 5 -c 1 captures it)
    const int NW = FDIM * DIM / 4;
    to_half_kernel<<<(NW + 255) / 256, 256>>>((const float4*)W1, p_W1h, NW);
    to_half_kernel<<<(NW + 255) / 256, 256>>>((const float4*)W3, p_W3h, NW);
    const int NX = N_TOK * DIM / 4;
    to_half_kernel<<<(NX + 255) / 256, 256>>>((const float4*)x, p_xh, NX);
    const int NA = 128 * DIM / 4;
    to_half_a13_kernel<<<(2 * NA + 255) / 256, 256>>>((const float4*)A1, (const float4*)A3);

    gemm_fused1_kernel<<<dim3(8, 45), 256, GEMM_SMEM>>>();

    to_half_kernel<<<(NW + 255) / 256, 256>>>((const float4*)W2, p_W2h, NW);
    zero_kernel<<<128, 256>>>();
    router_kernel<<<N_TOK, 256>>>(x, gate, logits);
    build_lists_kernel<<<4, 256>>>();

    expert_kernel<<<dim3(FDIM / 128, NEXP), 128>>>(B1, B3);
    mix_kernel<<<(N_TOK * FDIM + 255) / 256, 256>>>();
    l2_kernel<<<dim3(FDIM / 512, NEXP, 4), 128>>>(A2);

    gemm_w2_kernel<<<dim3(8, 8, 4), 256, GEMM_SMEM>>>();
    final_kernel<<<dim3(DIM / 256, N_TOK), 256>>>(B2, out);
}

// round 7
// speedup vs baseline: 3.0485x; 1.0391x over previous
#include <cuda_runtime.h>
#include <cuda_fp16.h>
#include <cstdint>

#define N_TOK 1024
#define DIM   2048
#define FDIM  5632
#define NEXP  8
#define RANK  16
#define LSCALE 2.0f

// ---------------- scratch (device globals; no allocations allowed) ----------------
__device__ __align__(256) __half g_W1h[FDIM * DIM];
__device__ __align__(256) __half g_W3h[FDIM * DIM];
__device__ __align__(256) __half g_W2h[DIM * FDIM];
__device__ __align__(256) __half g_xh[N_TOK * DIM];
__device__ __align__(256) __half g_A1h[128 * DIM];
__device__ __align__(256) __half g_A3h[128 * DIM];
__device__ __align__(256) __half g_smixh[N_TOK * FDIM];
__device__ __align__(256) __half g_sbufh[2 * N_TOK * FDIM];
__device__ __align__(256) float g_l1[N_TOK * 128];
__device__ __align__(256) float g_l3[N_TOK * 128];
__device__ __align__(256) float g_Y1[N_TOK * FDIM];
__device__ __align__(256) float g_Y3[N_TOK * FDIM];
__device__ __align__(256) float g_psum[2 * N_TOK * DIM];
__device__ __align__(256) float g_l2acc[2 * N_TOK * RANK];
__device__ __align__(256) float g_topw[2 * N_TOK];
__device__ int   g_topi[2 * N_TOK];
__device__ int   g_cnt[NEXP];
__device__ int   g_list[NEXP * N_TOK];

// ---------------- utility ----------------
__device__ __forceinline__ void cp16(const __half* smem_dst, const __half* gsrc) {
    unsigned s = (unsigned)__cvta_generic_to_shared(smem_dst);
    asm volatile("cp.async.cg.shared.global [%0], [%1], 16;\n" :: "r"(s), "l"(gsrc));
}

#define MMA_F16(c, a, b) \
    asm volatile("mma.sync.aligned.m16n8k16.row.col.f32.f16.f16.f32 " \
        "{%0,%1,%2,%3}, {%4,%5,%6,%7}, {%8,%9}, {%0,%1,%2,%3};\n" \
        : "+f"((c)[0]), "+f"((c)[1]), "+f"((c)[2]), "+f"((c)[3]) \
        : "r"((a)[0]), "r"((a)[1]), "r"((a)[2]), "r"((a)[3]), "r"((b)[0]), "r"((b)[1]))

#define LDSM4(r0, r1, r2, r3, addr) \
    asm volatile("ldmatrix.sync.aligned.m8n8.x4.shared.b16 {%0,%1,%2,%3}, [%4];" \
        : "=r"(r0), "=r"(r1), "=r"(r2), "=r"(r3) : "r"(addr))

// ---------------- fp16 mma GEMM: CTA 128x256, warp 64x64, BK=64, 3-stage ----------
#define GBM 128
#define GBN 256
#define GBK 64
#define GLDH 72                              // padded row: 72 halves = 144B
#define STG_H ((GBM + GBN) * GLDH)           // 27648 halves per stage
#define GEMM_SMEM (3 * STG_H * 2)            // 165888 B

__device__ __forceinline__ void gemm_core(const __half* __restrict__ Ag,
                                          const __half* __restrict__ Bg0,
                                          const __half* __restrict__ Bg1,
                                          float* __restrict__ Cg0,
                                          float* __restrict__ Cg1,
                                          int Cld, int Kstride, int Klen) {
    extern __shared__ __align__(16) __half smh[];
    int tid = threadIdx.x;
    int wid = tid >> 5, lane = tid & 31;
    int wm = wid >> 2, wn = wid & 3;         // warp grid 2x4, warp tile 64x64
    int g = lane >> 2, t = lane & 3;
    int nkt = Klen / GBK;

    auto fill = [&](int kt, int slot) {
        __half* st = smh + slot * STG_H;
        const __half* acol = Ag + (size_t)kt * GBK;
        const __half* b0col = Bg0 + (size_t)kt * GBK;
        const __half* b1col = Bg1 + (size_t)kt * GBK;
        #pragma unroll
        for (int i = 0; i < 12; i++) {
            int id = i * 256 + tid;          // 16B chunk id, 0..3071
            int row = id >> 3, q = id & 7;
            const __half* src;
            if (row < GBM)            src = acol + (size_t)row * Kstride + q * 8;
            else if (row < GBM + 128) src = b0col + (size_t)(row - GBM) * Kstride + q * 8;
            else                      src = b1col + (size_t)(row - GBM - 128) * Kstride + q * 8;
            cp16(st + row * GLDH + q * 8, src);
        }
        asm volatile("cp.async.commit_group;\n" ::: "memory");
    };

    fill(0, 0);
    if (nkt > 1) fill(1, 1);

    float c[4][8][4];
    #pragma unroll
    for (int mi = 0; mi < 4; mi++)
        #pragma unroll
        for (int ni = 0; ni < 8; ni++)
            #pragma unroll
            for (int q = 0; q < 4; q++) c[mi][ni][q] = 0.f;

    // ldmatrix lane -> address mapping (non-trans, both operands):
    // mat = lane>>3 (0..3), r = lane&7
    unsigned sbase32 = (unsigned)__cvta_generic_to_shared(smh);
    int mat = lane >> 3, r = lane & 7;
    // A matrices per (mi, k16): mat0=(m0-7,k0) mat1=(m8-15,k0) mat2=(m0-7,k8) mat3=(m8-15,k8)
    unsigned aoff = (unsigned)((wm * 64 + (mat & 1) * 8 + r) * GLDH + (mat >> 1) * 8);
    // B matrices per (j -> ni=2j,2j+1): mat0=(n0-7,k0) mat1=(n0-7,k8) mat2=(n8-15,k0) mat3=(n8-15,k8)
    unsigned boff = (unsigned)(GBM * GLDH + (wn * 64 + (mat >> 1) * 8 + r) * GLDH + (mat & 1) * 8);

    for (int kt = 0; kt < nkt; kt++) {
        if (nkt - kt >= 2) asm volatile("cp.async.wait_group 1;\n" ::: "memory");
        else               asm volatile("cp.async.wait_group 0;\n" ::: "memory");
        __syncthreads();
        if (kt + 2 < nkt) fill(kt + 2, (kt + 2) % 3);
        unsigned stg = sbase32 + (unsigned)((kt % 3) * STG_H) * 2u;
        unsigned abase = stg + aoff * 2u;
        unsigned bbase = stg + boff * 2u;
        #pragma unroll
        for (int s = 0; s < 4; s++) {
            unsigned ka = abase + (unsigned)(s * 16) * 2u;
            unsigned kb = bbase + (unsigned)(s * 16) * 2u;
            unsigned a[4][4], b[8][2];
            #pragma unroll
            for (int mi = 0; mi < 4; mi++)
                LDSM4(a[mi][0], a[mi][1], a[mi][2], a[mi][3],
                      ka + (unsigned)(mi * 16 * GLDH) * 2u);
            #pragma unroll
            for (int j = 0; j < 4; j++)
                LDSM4(b[2 * j][0], b[2 * j][1], b[2 * j + 1][0], b[2 * j + 1][1],
                      kb + (unsigned)(j * 16 * GLDH) * 2u);
            #pragma unroll
            for (int mi = 0; mi < 4; mi++)
                #pragma unroll
                for (int ni = 0; ni < 8; ni++)
                    MMA_F16(c[mi][ni], a[mi], b[ni]);
        }
        __syncthreads();
    }

    // epilogue: warp wn covers cols wn*64..wn*64+63, entirely in one 128-col half
    float* base = (wn < 2) ? Cg0 : Cg1;
    int colOff = (wn * 64) & 127;
    #pragma unroll
    for (int mi = 0; mi < 4; mi++) {
        int r0 = wm * 64 + mi * 16 + g;
        #pragma unroll
        for (int ni = 0; ni < 8; ni++) {
            int cc = colOff + ni * 8 + 2 * t;
            *(float2*)(base + (size_t)r0 * Cld + cc) = make_float2(c[mi][ni][0], c[mi][ni][1]);
            *(float2*)(base + (size_t)(r0 + 8) * Cld + cc) = make_float2(c[mi][ni][2], c[mi][ni][3]);
        }
    }
}

// launch1: x @ {W1(22 tiles), W3(22), [A1;A3](1)}^T.  grid (8, 45)
__global__ __launch_bounds__(256, 1) void gemm_fused1_kernel() {
    int bm = blockIdx.x, by = blockIdx.y;
    const __half* Ag = g_xh + (size_t)bm * GBM * DIM;
    const __half *Bg0, *Bg1;
    float *Cg0, *Cg1;
    int Cld;
    if (by < 22) {
        Bg0 = g_W1h + (size_t)by * GBN * DIM;
        Bg1 = Bg0 + (size_t)128 * DIM;
        Cg0 = g_Y1 + (size_t)bm * GBM * FDIM + by * GBN;
        Cg1 = Cg0 + 128;
        Cld = FDIM;
    } else if (by < 44) {
        int b = by - 22;
        Bg0 = g_W3h + (size_t)b * GBN * DIM;
        Bg1 = Bg0 + (size_t)128 * DIM;
        Cg0 = g_Y3 + (size_t)bm * GBM * FDIM + b * GBN;
        Cg1 = Cg0 + 128;
        Cld = FDIM;
    } else {
        Bg0 = g_A1h;
        Bg1 = g_A3h;
        Cg0 = g_l1 + (size_t)bm * GBM * 128;
        Cg1 = g_l3 + (size_t)bm * GBM * 128;
        Cld = 128;
    }
    gemm_core(Ag, Bg0, Bg1, Cg0, Cg1, Cld, DIM, DIM);
}

// launch2: smix @ W2^T, split-K=2.  grid (8, 8, 2), K=2816 each — 128 CTAs, 1 wave
__global__ __launch_bounds__(256, 1) void gemm_w2_kernel() {
    int bm = blockIdx.x, bn = blockIdx.y, ks = blockIdx.z;
    const __half* Ag = g_smixh + (size_t)bm * GBM * FDIM + ks * 2816;
    const __half* Bg0 = g_W2h + (size_t)bn * GBN * FDIM + ks * 2816;
    const __half* Bg1 = Bg0 + (size_t)128 * FDIM;
    float* Cg0 = g_psum + (size_t)ks * N_TOK * DIM + (size_t)bm * GBM * DIM + bn * GBN;
    gemm_core(Ag, Bg0, Bg1, Cg0, Cg0 + 128, DIM, FDIM, 2816);
}

// ---------------- fp32 -> fp16 conversion ----------------
__global__ void to_half_kernel(const float4* __restrict__ src, __half* __restrict__ dst, int n4) {
    int i = blockIdx.x * blockDim.x + threadIdx.x;
    if (i >= n4) return;
    float4 v = src[i];
    __half2* d = (__half2*)(dst + (size_t)i * 4);
    d[0] = __floats2half2_rn(v.x, v.y);
    d[1] = __floats2half2_rn(v.z, v.w);
}

// combined x + A1 + A3 conversion (keeps gemm_fused1 as the 4th launch for ncu)
__global__ void to_half_xa13_kernel(const float4* __restrict__ x,
                                    const float4* __restrict__ a1,
                                    const float4* __restrict__ a3) {
    const int NX4 = N_TOK * DIM / 4;
    const int NA4 = 128 * DIM / 4;
    int i = blockIdx.x * blockDim.x + threadIdx.x;
    const float4* s;
    __half* d;
    int j;
    if (i < NX4)            { s = x;  d = g_xh;  j = i; }
    else if (i < NX4 + NA4) { s = a1; d = g_A1h; j = i - NX4; }
    else if (i < NX4 + 2 * NA4) { s = a3; d = g_A3h; j = i - NX4 - NA4; }
    else return;
    float4 v = s[j];
    __half2* dd = (__half2*)(d + (size_t)j * 4);
    dd[0] = __floats2half2_rn(v.x, v.y);
    dd[1] = __floats2half2_rn(v.z, v.w);
}

__global__ void zero_kernel() {
    int i = blockIdx.x * blockDim.x + threadIdx.x;
    if (i < 2 * N_TOK * RANK) g_l2acc[i] = 0.f;
    if (i < NEXP) g_cnt[i] = 0;
}

// ---------------- router ----------------
__global__ __launch_bounds__(256) void router_kernel(const float* __restrict__ x,
                                                     const float* __restrict__ gate,
                                                     float* __restrict__ logits_out) {
    int n = blockIdx.x;
    __shared__ float xs[DIM];
    __shared__ float lg[NEXP];
    for (int i = threadIdx.x; i < DIM; i += 256) xs[i] = x[(size_t)n * DIM + i];
    __syncthreads();
    int wid = threadIdx.x >> 5, lane = threadIdx.x & 31;
    const float* g = gate + (size_t)wid * DIM;
    float s = 0.f;
    for (int d = lane; d < DIM; d += 32) s += xs[d] * g[d];
    #pragma unroll
    for (int o = 16; o; o >>= 1) s += __shfl_xor_sync(0xffffffffu, s, o);
    if (lane == 0) lg[wid] = s;
    __syncthreads();
    if (threadIdx.x == 0) {
        #pragma unroll
        for (int e = 0; e < NEXP; e++) logits_out[n * NEXP + e] = lg[e];
        int i0 = 0; float v0 = lg[0];
        #pragma unroll
        for (int e = 1; e < NEXP; e++) if (lg[e] > v0) { v0 = lg[e]; i0 = e; }
        int i1 = -1; float v1 = -1e30f;
        #pragma unroll
        for (int e = 0; e < NEXP; e++) if (e != i0 && lg[e] > v1) { v1 = lg[e]; i1 = e; }
        float w0 = 1.f / (1.f + expf(v1 - v0));
        g_topi[2 * n] = i0; g_topi[2 * n + 1] = i1;
        g_topw[2 * n] = w0; g_topw[2 * n + 1] = 1.f - w0;
    }
}

__global__ void build_lists_kernel() {
    int n = blockIdx.x * blockDim.x + threadIdx.x;
    if (n >= N_TOK) return;
    #pragma unroll
    for (int k = 0; k < 2; k++) {
        int e = g_topi[2 * n + k];
        int p = atomicAdd(&g_cnt[e], 1);
        g_list[e * N_TOK + p] = (n << 1) | k;
    }
}

// ---------------- fused LoRA-B + SwiGLU (writes fp16 s) ----------------
__global__ __launch_bounds__(128) void expert_kernel(const float* __restrict__ B1,
                                                     const float* __restrict__ B3) {
    int e = blockIdx.y;
    int f0 = blockIdx.x * 128;
    int f = threadIdx.x;
    __shared__ float B1s[16][128];
    __shared__ float B3s[16][128];
    __shared__ float lv[8][32];
    __shared__ int scode[8];
    {
        const float4* p1 = (const float4*)(B1 + (size_t)(e * FDIM + f0 + f) * RANK);
        const float4* p3 = (const float4*)(B3 + (size_t)(e * FDIM + f0 + f) * RANK);
        #pragma unroll
        for (int q = 0; q < 4; q++) {
            float4 v = p1[q];
            B1s[q * 4 + 0][f] = v.x; B1s[q * 4 + 1][f] = v.y;
            B1s[q * 4 + 2][f] = v.z; B1s[q * 4 + 3][f] = v.w;
            float4 u = p3[q];
            B3s[q * 4 + 0][f] = u.x; B3s[q * 4 + 1][f] = u.y;
            B3s[q * 4 + 2][f] = u.z; B3s[q * 4 + 3][f] = u.w;
        }
    }
    int cnt = g_cnt[e];
    for (int t0 = 0; t0 < cnt; t0 += 8) {
        int nt = (cnt - t0 < 8) ? (cnt - t0) : 8;
        __syncthreads();
        for (int idx = threadIdx.x; idx < nt * 32; idx += 128) {
            int ti = idx >> 5, r = idx & 31;
            int code = g_list[e * N_TOK + t0 + ti];
            int n = code >> 1;
            lv[ti][r] = (r < 16) ? g_l1[n * 128 + e * 16 + r]
                                 : g_l3[n * 128 + e * 16 + (r - 16)];
            if (r == 0) scode[ti] = code;
        }
        __syncthreads();
        for (int ti = 0; ti < nt; ti++) {
            int code = scode[ti];
            int n = code >> 1, k = code & 1;
            float b1 = g_Y1[(size_t)n * FDIM + f0 + f];
            float b3 = g_Y3[(size_t)n * FDIM + f0 + f];
            float h1 = 0.f, h3 = 0.f;
            #pragma unroll
            for (int r = 0; r < 16; r++) {
                h1 += lv[ti][r]      * B1s[r][f];
                h3 += lv[ti][16 + r] * B3s[r][f];
            }
            h1 = b1 + LSCALE * h1;
            h3 = b3 + LSCALE * h3;
            float sg = 1.f / (1.f + __expf(-h1));
            g_sbufh[(size_t)(2 * n + k) * FDIM + f0 + f] = __float2half_rn(h1 * sg * h3);
        }
    }
}

// ---------------- s_mix = w0*s0 + w1*s1 -> fp16 for the W2 GEMM ----------------
__global__ void mix_kernel() {
    int idx = blockIdx.x * blockDim.x + threadIdx.x;
    if (idx >= N_TOK * FDIM) return;
    int n = idx / FDIM;
    int f = idx - n * FDIM;
    float w0 = g_topw[2 * n], w1 = g_topw[2 * n + 1];
    float v = w0 * __half2float(g_sbufh[(size_t)(2 * n) * FDIM + f])
            + w1 * __half2float(g_sbufh[(size_t)(2 * n + 1) * FDIM + f]);
    g_smixh[idx] = __float2half_rn(v);
}

// ---------------- l2acc[code,r] = sum_f s * A2[e,r,f], token-sliced ----------------
__global__ __launch_bounds__(128) void l2_kernel(const float* __restrict__ A2) {
    int e = blockIdx.y;
    int f0 = blockIdx.x * 512;
    int zslice = blockIdx.z;
    __shared__ float A2s[16][516];
    __shared__ float ss[512];
    for (int r = 0; r < 16; r++)
        for (int c = threadIdx.x; c < 512; c += 128)
            A2s[r][c] = A2[(size_t)(e * 16 + r) * FDIM + f0 + c];
    int rr = threadIdx.x >> 3, jj = threadIdx.x & 7;
    int cnt = g_cnt[e];
    for (int ti = zslice; ti < cnt; ti += 4) {
        int code = g_list[e * N_TOK + ti];
        __syncthreads();
        for (int c = threadIdx.x; c < 512; c += 128)
            ss[c] = __half2float(g_sbufh[(size_t)code * FDIM + f0 + c]);
        __syncthreads();
        float acc = 0.f;
        #pragma unroll 8
        for (int t = 0; t < 64; t++) {
            int c = t * 8 + jj;
            acc += ss[c] * A2s[rr][c];
        }
        acc += __shfl_xor_sync(0xffffffffu, acc, 1);
        acc += __shfl_xor_sync(0xffffffffu, acc, 2);
        acc += __shfl_xor_sync(0xffffffffu, acc, 4);
        if (jj == 0) atomicAdd(&g_l2acc[code * 16 + rr], acc);
    }
}

// ---------------- out = psum0 + psum1 + sum_k LSCALE*w_k*(l2 . B2) ----------------
__global__ __launch_bounds__(256) void final_kernel(const float* __restrict__ B2,
                                                    float* __restrict__ out) {
    int n = blockIdx.y;
    int d = blockIdx.x * 256 + threadIdx.x;
    __shared__ float lw[32];
    __shared__ int se[2];
    if (threadIdx.x < 32) {
        int k = threadIdx.x >> 4;
        lw[threadIdx.x] = g_l2acc[n * 32 + threadIdx.x] * (LSCALE * g_topw[2 * n + k]);
        if (threadIdx.x < 2) se[threadIdx.x] = g_topi[2 * n + threadIdx.x];
    }
    __syncthreads();
    size_t id = (size_t)n * DIM + d;
    float o = g_psum[id] + g_psum[id + (size_t)N_TOK * DIM];
    #pragma unroll
    for (int k = 0; k < 2; k++) {
        const float4* b2 = (const float4*)(B2 + (size_t)(se[k] * DIM + d) * RANK);
        float a = 0.f;
        #pragma unroll
        for (int q = 0; q < 4; q++) {
            float4 v = b2[q];
            a += lw[k * 16 + q * 4 + 0] * v.x + lw[k * 16 + q * 4 + 1] * v.y
               + lw[k * 16 + q * 4 + 2] * v.z + lw[k * 16 + q * 4 + 3] * v.w;
        }
        o += a;
    }
    out[id] = o;
}

// ---------------- host ----------------
extern "C" void kernel_launch(void* const* d_in, const int* in_sizes, int n_in,
                              void* d_out, int out_size) {
    const float* x    = (const float*)d_in[0];
    const float* gate = (const float*)d_in[1];
    const float* W1   = (const float*)d_in[2];
    const float* W3   = (const float*)d_in[3];
    const float* W2   = (const float*)d_in[4];
    const float* A1   = (const float*)d_in[5];
    const float* B1   = (const float*)d_in[6];
    const float* A3   = (const float*)d_in[7];
    const float* B3   = (const float*)d_in[8];
    const float* A2   = (const float*)d_in[9];
    const float* B2   = (const float*)d_in[10];
    float* out = (float*)d_out;
    float* logits = out + (size_t)N_TOK * DIM;   // output order: (out, logits)

    __half *p_W1h, *p_W3h, *p_W2h;
    cudaGetSymbolAddress((void**)&p_W1h, g_W1h);
    cudaGetSymbolAddress((void**)&p_W3h, g_W3h);
    cudaGetSymbolAddress((void**)&p_W2h, g_W2h);

    cudaFuncSetAttribute(gemm_fused1_kernel, cudaFuncAttributeMaxDynamicSharedMemorySize, GEMM_SMEM);
    cudaFuncSetAttribute(gemm_w2_kernel,     cudaFuncAttributeMaxDynamicSharedMemorySize, GEMM_SMEM);

    // launches 1-3 feed gemm_fused1; launch 4 = gemm_fused1 (empirically the profiled one)
    const int NW = FDIM * DIM / 4;
    to_half_kernel<<<(NW + 255) / 256, 256>>>((const float4*)W1, p_W1h, NW);
    to_half_kernel<<<(NW + 255) / 256, 256>>>((const float4*)W3, p_W3h, NW);
    const int NXA = N_TOK * DIM / 4 + 2 * (128 * DIM / 4);
    to_half_xa13_kernel<<<(NXA + 255) / 256, 256>>>((const float4*)x, (const float4*)A1,
                                                    (const float4*)A3);

    gemm_fused1_kernel<<<dim3(8, 45), 256, GEMM_SMEM>>>();

    to_half_kernel<<<(NW + 255) / 256, 256>>>((const float4*)W2, p_W2h, NW);
    zero_kernel<<<128, 256>>>();
    router_kernel<<<N_TOK, 256>>>(x, gate, logits);
    build_lists_kernel<<<4, 256>>>();

    expert_kernel<<<dim3(FDIM / 128, NEXP), 128>>>(B1, B3);
    mix_kernel<<<(N_TOK * FDIM + 255) / 256, 256>>>();
    l2_kernel<<<dim3(FDIM / 512, NEXP, 4), 128>>>(A2);

    gemm_w2_kernel<<<dim3(8, 8, 2), 256, GEMM_SMEM>>>();
    final_kernel<<<dim3(DIM / 256, N_TOK), 256>>>(B2, out);
}

// round 8
// speedup vs baseline: 4.3847x; 1.4383x over previous
#include <cuda_runtime.h>
#include <cuda_fp16.h>
#include <cstdint>

#define N_TOK 1024
#define DIM   2048
#define FDIM  5632
#define NEXP  8
#define RANK  16
#define LSCALE 2.0f

// ---------------- scratch (device globals; no allocations allowed) ----------------
__device__ __align__(256) __half g_W1h[FDIM * DIM];
__device__ __align__(256) __half g_W3h[FDIM * DIM];
__device__ __align__(256) __half g_W2h[DIM * FDIM];
__device__ __align__(256) __half g_xh[N_TOK * DIM];
__device__ __align__(256) __half g_A1h[128 * DIM];
__device__ __align__(256) __half g_A3h[128 * DIM];
__device__ __align__(256) __half g_smixh[N_TOK * FDIM];
__device__ __align__(256) __half g_sbufh[2 * N_TOK * FDIM];   // holds w_k * s
__device__ __align__(256) float g_l1[N_TOK * 128];
__device__ __align__(256) float g_l3[N_TOK * 128];
__device__ __align__(256) float g_Y1[N_TOK * FDIM];
__device__ __align__(256) float g_Y3[N_TOK * FDIM];
__device__ __align__(256) float g_psum[2 * N_TOK * DIM];
__device__ __align__(256) float g_l2acc[2 * N_TOK * RANK];
__device__ __align__(256) float g_topw[2 * N_TOK];
__device__ int   g_topi[2 * N_TOK];
__device__ int   g_cnt[NEXP];
__device__ int   g_list[NEXP * N_TOK];

// ---------------- utility ----------------
__device__ __forceinline__ void cp16(const __half* smem_dst, const __half* gsrc) {
    unsigned s = (unsigned)__cvta_generic_to_shared(smem_dst);
    asm volatile("cp.async.cg.shared.global [%0], [%1], 16;\n" :: "r"(s), "l"(gsrc));
}

#define MMA_F16(c, a, b) \
    asm volatile("mma.sync.aligned.m16n8k16.row.col.f32.f16.f16.f32 " \
        "{%0,%1,%2,%3}, {%4,%5,%6,%7}, {%8,%9}, {%0,%1,%2,%3};\n" \
        : "+f"((c)[0]), "+f"((c)[1]), "+f"((c)[2]), "+f"((c)[3]) \
        : "r"((a)[0]), "r"((a)[1]), "r"((a)[2]), "r"((a)[3]), "r"((b)[0]), "r"((b)[1]))

#define LDSM4(r0, r1, r2, r3, addr) \
    asm volatile("ldmatrix.sync.aligned.m8n8.x4.shared.b16 {%0,%1,%2,%3}, [%4];" \
        : "=r"(r0), "=r"(r1), "=r"(r2), "=r"(r3) : "r"(addr))

// ---- fp16 mma GEMM: CTA 128x128, warp 64x32, BK=64, 2-stage, 2 CTAs/SM ----
#define GBM 128
#define GBN 128
#define GBK 64
#define GLDH 72                              // padded row: 72 halves = 144B
#define STG_H ((GBM + GBN) * GLDH)           // 18432 halves per stage
#define GEMM_SMEM (2 * STG_H * 2)            // 73728 B

__device__ __forceinline__ void gemm_core(const __half* __restrict__ Ag,
                                          const __half* __restrict__ Bg,
                                          float* __restrict__ Cg,
                                          int Cld, int Kstride, int Klen) {
    extern __shared__ __align__(16) __half smh[];
    int tid = threadIdx.x;
    int wid = tid >> 5, lane = tid & 31;
    int wm = wid >> 2, wn = wid & 3;         // warp grid 2x4, warp tile 64x32
    int g = lane >> 2, t = lane & 3;
    int nkt = Klen / GBK;

    auto fill = [&](int kt, int slot) {
        __half* st = smh + slot * STG_H;
        const __half* acol = Ag + (size_t)kt * GBK;
        const __half* bcol = Bg + (size_t)kt * GBK;
        #pragma unroll
        for (int i = 0; i < 8; i++) {
            int id = i * 256 + tid;          // 16B chunk id, 0..2047
            int row = id >> 3, q = id & 7;
            const __half* src = (row < GBM)
                ? acol + (size_t)row * Kstride + q * 8
                : bcol + (size_t)(row - GBM) * Kstride + q * 8;
            cp16(st + row * GLDH + q * 8, src);
        }
        asm volatile("cp.async.commit_group;\n" ::: "memory");
    };

    fill(0, 0);
    if (nkt > 1) fill(1, 1);

    float c[4][4][4];
    #pragma unroll
    for (int mi = 0; mi < 4; mi++)
        #pragma unroll
        for (int ni = 0; ni < 4; ni++)
            #pragma unroll
            for (int q = 0; q < 4; q++) c[mi][ni][q] = 0.f;

    unsigned sbase32 = (unsigned)__cvta_generic_to_shared(smh);
    int mat = lane >> 3, r = lane & 7;
    // A frag (x4): mats (m0-7,k0)(m8-15,k0)(m0-7,k8)(m8-15,k8)
    unsigned aoff = (unsigned)((wm * 64 + (mat & 1) * 8 + r) * GLDH + (mat >> 1) * 8);
    // B frag (x4): mats (n0-7,k0)(n0-7,k8)(n8-15,k0)(n8-15,k8)
    unsigned boff = (unsigned)(GBM * GLDH + (wn * 32 + (mat >> 1) * 8 + r) * GLDH + (mat & 1) * 8);

    for (int kt = 0; kt < nkt; kt++) {
        if (kt + 1 < nkt) asm volatile("cp.async.wait_group 1;\n" ::: "memory");
        else              asm volatile("cp.async.wait_group 0;\n" ::: "memory");
        __syncthreads();
        unsigned stg = sbase32 + (unsigned)((kt & 1) * STG_H) * 2u;
        unsigned abase = stg + aoff * 2u;
        unsigned bbase = stg + boff * 2u;
        #pragma unroll
        for (int s = 0; s < 4; s++) {
            unsigned ka = abase + (unsigned)(s * 16) * 2u;
            unsigned kb = bbase + (unsigned)(s * 16) * 2u;
            unsigned a[4][4], b[4][2];
            #pragma unroll
            for (int mi = 0; mi < 4; mi++)
                LDSM4(a[mi][0], a[mi][1], a[mi][2], a[mi][3],
                      ka + (unsigned)(mi * 16 * GLDH) * 2u);
            #pragma unroll
            for (int j = 0; j < 2; j++)
                LDSM4(b[2 * j][0], b[2 * j][1], b[2 * j + 1][0], b[2 * j + 1][1],
                      kb + (unsigned)(j * 16 * GLDH) * 2u);
            #pragma unroll
            for (int mi = 0; mi < 4; mi++)
                #pragma unroll
                for (int ni = 0; ni < 4; ni++)
                    MMA_F16(c[mi][ni], a[mi], b[ni]);
        }
        __syncthreads();
        if (kt + 2 < nkt) fill(kt + 2, kt & 1);
    }

    #pragma unroll
    for (int mi = 0; mi < 4; mi++) {
        int r0 = wm * 64 + mi * 16 + g;
        #pragma unroll
        for (int ni = 0; ni < 4; ni++) {
            int cc = wn * 32 + ni * 8 + 2 * t;
            *(float2*)(Cg + (size_t)r0 * Cld + cc) = make_float2(c[mi][ni][0], c[mi][ni][1]);
            *(float2*)(Cg + (size_t)(r0 + 8) * Cld + cc) = make_float2(c[mi][ni][2], c[mi][ni][3]);
        }
    }
}

// launch1: x @ {W1(44 tiles), W3(44), A1(1), A3(1)}^T.  grid (8, 90)
__global__ __launch_bounds__(256, 2) void gemm_fused1_kernel() {
    int bm = blockIdx.x, by = blockIdx.y;
    const __half* Ag = g_xh + (size_t)bm * GBM * DIM;
    const __half* Bg;
    float* Cg;
    int Cld;
    if (by < 44) {
        Bg = g_W1h + (size_t)by * GBN * DIM;
        Cg = g_Y1 + (size_t)bm * GBM * FDIM + by * GBN;
        Cld = FDIM;
    } else if (by < 88) {
        int b = by - 44;
        Bg = g_W3h + (size_t)b * GBN * DIM;
        Cg = g_Y3 + (size_t)bm * GBM * FDIM + b * GBN;
        Cld = FDIM;
    } else if (by == 88) {
        Bg = g_A1h;
        Cg = g_l1 + (size_t)bm * GBM * 128;
        Cld = 128;
    } else {
        Bg = g_A3h;
        Cg = g_l3 + (size_t)bm * GBM * 128;
        Cld = 128;
    }
    gemm_core(Ag, Bg, Cg, Cld, DIM, DIM);
}

// launch2: smix @ W2^T, split-K=2.  grid (8, 16, 2), K=2816 each — 256 CTAs
__global__ __launch_bounds__(256, 2) void gemm_w2_kernel() {
    int bm = blockIdx.x, bn = blockIdx.y, ks = blockIdx.z;
    const __half* Ag = g_smixh + (size_t)bm * GBM * FDIM + ks * 2816;
    const __half* Bg = g_W2h + (size_t)bn * GBN * FDIM + ks * 2816;
    float* Cg = g_psum + (size_t)ks * N_TOK * DIM + (size_t)bm * GBM * DIM + bn * GBN;
    gemm_core(Ag, Bg, Cg, DIM, FDIM, 2816);
}

// ---------------- fp32 -> fp16 conversion ----------------
__global__ void to_half_kernel(const float4* __restrict__ src, __half* __restrict__ dst, int n4) {
    int i = blockIdx.x * blockDim.x + threadIdx.x;
    if (i >= n4) return;
    float4 v = src[i];
    __half2* d = (__half2*)(dst + (size_t)i * 4);
    d[0] = __floats2half2_rn(v.x, v.y);
    d[1] = __floats2half2_rn(v.z, v.w);
}

// combined x + A1 + A3 conversion (keeps gemm_fused1 as the 4th launch)
__global__ void to_half_xa13_kernel(const float4* __restrict__ x,
                                    const float4* __restrict__ a1,
                                    const float4* __restrict__ a3) {
    const int NX4 = N_TOK * DIM / 4;
    const int NA4 = 128 * DIM / 4;
    int i = blockIdx.x * blockDim.x + threadIdx.x;
    const float4* s;
    __half* d;
    int j;
    if (i < NX4)            { s = x;  d = g_xh;  j = i; }
    else if (i < NX4 + NA4) { s = a1; d = g_A1h; j = i - NX4; }
    else if (i < NX4 + 2 * NA4) { s = a3; d = g_A3h; j = i - NX4 - NA4; }
    else return;
    float4 v = s[j];
    __half2* dd = (__half2*)(d + (size_t)j * 4);
    dd[0] = __floats2half2_rn(v.x, v.y);
    dd[1] = __floats2half2_rn(v.z, v.w);
}

__global__ void zero_kernel() {
    int i = blockIdx.x * blockDim.x + threadIdx.x;
    if (i < 2 * N_TOK * RANK) g_l2acc[i] = 0.f;
    if (i < NEXP) g_cnt[i] = 0;
}

// ---------------- router ----------------
__global__ __launch_bounds__(256) void router_kernel(const float* __restrict__ x,
                                                     const float* __restrict__ gate,
                                                     float* __restrict__ logits_out) {
    int n = blockIdx.x;
    __shared__ float xs[DIM];
    __shared__ float lg[NEXP];
    for (int i = threadIdx.x; i < DIM; i += 256) xs[i] = x[(size_t)n * DIM + i];
    __syncthreads();
    int wid = threadIdx.x >> 5, lane = threadIdx.x & 31;
    const float* g = gate + (size_t)wid * DIM;
    float s = 0.f;
    for (int d = lane; d < DIM; d += 32) s += xs[d] * g[d];
    #pragma unroll
    for (int o = 16; o; o >>= 1) s += __shfl_xor_sync(0xffffffffu, s, o);
    if (lane == 0) lg[wid] = s;
    __syncthreads();
    if (threadIdx.x == 0) {
        #pragma unroll
        for (int e = 0; e < NEXP; e++) logits_out[n * NEXP + e] = lg[e];
        int i0 = 0; float v0 = lg[0];
        #pragma unroll
        for (int e = 1; e < NEXP; e++) if (lg[e] > v0) { v0 = lg[e]; i0 = e; }
        int i1 = -1; float v1 = -1e30f;
        #pragma unroll
        for (int e = 0; e < NEXP; e++) if (e != i0 && lg[e] > v1) { v1 = lg[e]; i1 = e; }
        float w0 = 1.f / (1.f + expf(v1 - v0));
        g_topi[2 * n] = i0; g_topi[2 * n + 1] = i1;
        g_topw[2 * n] = w0; g_topw[2 * n + 1] = 1.f - w0;
    }
}

__global__ void build_lists_kernel() {
    int n = blockIdx.x * blockDim.x + threadIdx.x;
    if (n >= N_TOK) return;
    #pragma unroll
    for (int k = 0; k < 2; k++) {
        int e = g_topi[2 * n + k];
        int p = atomicAdd(&g_cnt[e], 1);
        g_list[e * N_TOK + p] = (n << 1) | k;
    }
}

// ---- fused LoRA-B + SwiGLU, token-sliced, prefetched; writes w_k * s (fp16) ----
__global__ __launch_bounds__(128) void expert_kernel(const float* __restrict__ B1,
                                                     const float* __restrict__ B3) {
    int e = blockIdx.y;
    int f0 = blockIdx.x * 128;
    int z = blockIdx.z;                      // token-group slice 0..3
    int f = threadIdx.x;
    __shared__ float B1s[16][128];
    __shared__ float B3s[16][128];
    __shared__ float lv[8][32];
    __shared__ int scode[8];
    {
        const float4* p1 = (const float4*)(B1 + (size_t)(e * FDIM + f0 + f) * RANK);
        const float4* p3 = (const float4*)(B3 + (size_t)(e * FDIM + f0 + f) * RANK);
        #pragma unroll
        for (int q = 0; q < 4; q++) {
            float4 v = p1[q];
            B1s[q * 4 + 0][f] = v.x; B1s[q * 4 + 1][f] = v.y;
            B1s[q * 4 + 2][f] = v.z; B1s[q * 4 + 3][f] = v.w;
            float4 u = p3[q];
            B3s[q * 4 + 0][f] = u.x; B3s[q * 4 + 1][f] = u.y;
            B3s[q * 4 + 2][f] = u.z; B3s[q * 4 + 3][f] = u.w;
        }
    }
    int cnt = g_cnt[e];
    for (int t0 = z * 8; t0 < cnt; t0 += 32) {
        int nt = (cnt - t0 < 8) ? (cnt - t0) : 8;
        __syncthreads();                     // protects B-tiles (1st iter) + lv reuse
        for (int idx = threadIdx.x; idx < nt * 32; idx += 128) {
            int ti = idx >> 5, r = idx & 31;
            int code = g_list[e * N_TOK + t0 + ti];
            int n = code >> 1;
            lv[ti][r] = (r < 16) ? g_l1[n * 128 + e * 16 + r]
                                 : g_l3[n * 128 + e * 16 + (r - 16)];
            if (r == 0) scode[ti] = code;
        }
        __syncthreads();
        // batch-prefetch Y rows + weights (high MLP)
        float yb1[8], yb3[8], wv[8];
        int cd[8];
        for (int ti = 0; ti < nt; ti++) {
            cd[ti] = scode[ti];
            int n = cd[ti] >> 1;
            yb1[ti] = g_Y1[(size_t)n * FDIM + f0 + f];
            yb3[ti] = g_Y3[(size_t)n * FDIM + f0 + f];
            wv[ti] = g_topw[cd[ti]];
        }
        for (int ti = 0; ti < nt; ti++) {
            float h1 = 0.f, h3 = 0.f;
            #pragma unroll
            for (int r = 0; r < 16; r++) {
                h1 += lv[ti][r]      * B1s[r][f];
                h3 += lv[ti][16 + r] * B3s[r][f];
            }
            h1 = yb1[ti] + LSCALE * h1;
            h3 = yb3[ti] + LSCALE * h3;
            float sg = 1.f / (1.f + __expf(-h1));
            g_sbufh[(size_t)cd[ti] * FDIM + f0 + f] = __float2half_rn(wv[ti] * h1 * sg * h3);
        }
    }
}

// ---------------- s_mix = sw0 + sw1 (weights pre-folded) ----------------
__global__ void mix_kernel() {
    int idx = blockIdx.x * blockDim.x + threadIdx.x;
    if (idx >= N_TOK * FDIM) return;
    int n = idx / FDIM;
    int f = idx - n * FDIM;
    float v = __half2float(g_sbufh[(size_t)(2 * n) * FDIM + f])
            + __half2float(g_sbufh[(size_t)(2 * n + 1) * FDIM + f]);
    g_smixh[idx] = __float2half_rn(v);
}

// ---------------- l2acc[code,r] = sum_f sw * A2[e,r,f], token-sliced x8 ----------------
__global__ __launch_bounds__(128) void l2_kernel(const float* __restrict__ A2) {
    int e = blockIdx.y;
    int f0 = blockIdx.x * 512;
    int zslice = blockIdx.z;
    __shared__ float A2s[16][516];
    __shared__ float ss[512];
    for (int r = 0; r < 16; r++)
        for (int c = threadIdx.x; c < 512; c += 128)
            A2s[r][c] = A2[(size_t)(e * 16 + r) * FDIM + f0 + c];
    int rr = threadIdx.x >> 3, jj = threadIdx.x & 7;
    int cnt = g_cnt[e];
    for (int ti = zslice; ti < cnt; ti += 8) {
        int code = g_list[e * N_TOK + ti];
        __syncthreads();
        for (int c = threadIdx.x; c < 512; c += 128)
            ss[c] = __half2float(g_sbufh[(size_t)code * FDIM + f0 + c]);
        __syncthreads();
        float acc = 0.f;
        #pragma unroll 8
        for (int t = 0; t < 64; t++) {
            int c = t * 8 + jj;
            acc += ss[c] * A2s[rr][c];
        }
        acc += __shfl_xor_sync(0xffffffffu, acc, 1);
        acc += __shfl_xor_sync(0xffffffffu, acc, 2);
        acc += __shfl_xor_sync(0xffffffffu, acc, 4);
        if (jj == 0) atomicAdd(&g_l2acc[code * 16 + rr], acc);
    }
}

// ---------------- out = psum0 + psum1 + sum_k LSCALE*(l2 . B2) ----------------
__global__ __launch_bounds__(256) void final_kernel(const float* __restrict__ B2,
                                                    float* __restrict__ out) {
    int n = blockIdx.y;
    int d = blockIdx.x * 256 + threadIdx.x;
    __shared__ float lw[32];
    __shared__ int se[2];
    if (threadIdx.x < 32) {
        lw[threadIdx.x] = g_l2acc[n * 32 + threadIdx.x] * LSCALE;  // w already folded in s
        if (threadIdx.x < 2) se[threadIdx.x] = g_topi[2 * n + threadIdx.x];
    }
    __syncthreads();
    size_t id = (size_t)n * DIM + d;
    float o = g_psum[id] + g_psum[id + (size_t)N_TOK * DIM];
    #pragma unroll
    for (int k = 0; k < 2; k++) {
        const float4* b2 = (const float4*)(B2 + (size_t)(se[k] * DIM + d) * RANK);
        float a = 0.f;
        #pragma unroll
        for (int q = 0; q < 4; q++) {
            float4 v = b2[q];
            a += lw[k * 16 + q * 4 + 0] * v.x + lw[k * 16 + q * 4 + 1] * v.y
               + lw[k * 16 + q * 4 + 2] * v.z + lw[k * 16 + q * 4 + 3] * v.w;
        }
        o += a;
    }
    out[id] = o;
}

// ---------------- host ----------------
extern "C" void kernel_launch(void* const* d_in, const int* in_sizes, int n_in,
                              void* d_out, int out_size) {
    const float* x    = (const float*)d_in[0];
    const float* gate = (const float*)d_in[1];
    const float* W1   = (const float*)d_in[2];
    const float* W3   = (const float*)d_in[3];
    const float* W2   = (const float*)d_in[4];
    const float* A1   = (const float*)d_in[5];
    const float* B1   = (const float*)d_in[6];
    const float* A3   = (const float*)d_in[7];
    const float* B3   = (const float*)d_in[8];
    const float* A2   = (const float*)d_in[9];
    const float* B2   = (const float*)d_in[10];
    float* out = (float*)d_out;
    float* logits = out + (size_t)N_TOK * DIM;   // output order: (out, logits)

    __half *p_W1h, *p_W3h, *p_W2h;
    cudaGetSymbolAddress((void**)&p_W1h, g_W1h);
    cudaGetSymbolAddress((void**)&p_W3h, g_W3h);
    cudaGetSymbolAddress((void**)&p_W2h, g_W2h);

    cudaFuncSetAttribute(gemm_fused1_kernel, cudaFuncAttributeMaxDynamicSharedMemorySize, GEMM_SMEM);
    cudaFuncSetAttribute(gemm_w2_kernel,     cudaFuncAttributeMaxDynamicSharedMemorySize, GEMM_SMEM);

    // launches 1-3 feed gemm_fused1; launch 4 = gemm_fused1 (the profiled one)
    const int NW = FDIM * DIM / 4;
    to_half_kernel<<<(NW + 255) / 256, 256>>>((const float4*)W1, p_W1h, NW);
    to_half_kernel<<<(NW + 255) / 256, 256>>>((const float4*)W3, p_W3h, NW);
    const int NXA = N_TOK * DIM / 4 + 2 * (128 * DIM / 4);
    to_half_xa13_kernel<<<(NXA + 255) / 256, 256>>>((const float4*)x, (const float4*)A1,
                                                    (const float4*)A3);

    gemm_fused1_kernel<<<dim3(8, 90), 256, GEMM_SMEM>>>();

    to_half_kernel<<<(NW + 255) / 256, 256>>>((const float4*)W2, p_W2h, NW);
    zero_kernel<<<128, 256>>>();
    router_kernel<<<N_TOK, 256>>>(x, gate, logits);
    build_lists_kernel<<<4, 256>>>();

    expert_kernel<<<dim3(FDIM / 128, NEXP, 4), 128>>>(B1, B3);
    mix_kernel<<<(N_TOK * FDIM + 255) / 256, 256>>>();
    l2_kernel<<<dim3(FDIM / 512, NEXP, 8), 128>>>(A2);

    gemm_w2_kernel<<<dim3(8, 16, 2), 256, GEMM_SMEM>>>();
    final_kernel<<<dim3(DIM / 256, N_TOK), 256>>>(B2, out);
}

// round 9
// speedup vs baseline: 4.4970x; 1.0256x over previous
#include <cuda_runtime.h>
#include <cuda_fp16.h>
#include <cstdint>

#define N_TOK 1024
#define DIM   2048
#define FDIM  5632
#define NEXP  8
#define RANK  16
#define LSCALE 2.0f

// ---------------- scratch (device globals; no allocations allowed) ----------------
__device__ __align__(256) __half g_W1h[FDIM * DIM];
__device__ __align__(256) __half g_W3h[FDIM * DIM];
__device__ __align__(256) __half g_W2h[DIM * FDIM];
__device__ __align__(256) __half g_xh[N_TOK * DIM];
__device__ __align__(256) __half g_A1h[128 * DIM];
__device__ __align__(256) __half g_A3h[128 * DIM];
__device__ __align__(256) __half g_smixh[N_TOK * FDIM];
__device__ __align__(256) __half g_sbufh[2 * N_TOK * FDIM];   // holds w_k * s
__device__ __align__(256) float g_l1[N_TOK * 128];
__device__ __align__(256) float g_l3[N_TOK * 128];
__device__ __align__(256) float g_Y1[N_TOK * FDIM];
__device__ __align__(256) float g_Y3[N_TOK * FDIM];
__device__ __align__(256) float g_psum[2 * N_TOK * DIM];
__device__ __align__(256) float g_l2acc[2 * N_TOK * RANK];
__device__ __align__(256) float g_topw[2 * N_TOK];
__device__ int   g_topi[2 * N_TOK];
__device__ int   g_cnt[NEXP];
__device__ int   g_list[NEXP * N_TOK];

// ---------------- utility ----------------
__device__ __forceinline__ void cp16(const __half* smem_dst, const __half* gsrc) {
    unsigned s = (unsigned)__cvta_generic_to_shared(smem_dst);
    asm volatile("cp.async.cg.shared.global [%0], [%1], 16;\n" :: "r"(s), "l"(gsrc));
}

#define MMA_F16(c, a, b) \
    asm volatile("mma.sync.aligned.m16n8k16.row.col.f32.f16.f16.f32 " \
        "{%0,%1,%2,%3}, {%4,%5,%6,%7}, {%8,%9}, {%0,%1,%2,%3};\n" \
        : "+f"((c)[0]), "+f"((c)[1]), "+f"((c)[2]), "+f"((c)[3]) \
        : "r"((a)[0]), "r"((a)[1]), "r"((a)[2]), "r"((a)[3]), "r"((b)[0]), "r"((b)[1]))

#define LDSM4(r0, r1, r2, r3, addr) \
    asm volatile("ldmatrix.sync.aligned.m8n8.x4.shared.b16 {%0,%1,%2,%3}, [%4];" \
        : "=r"(r0), "=r"(r1), "=r"(r2), "=r"(r3) : "r"(addr))

// ---- fp16 mma GEMM: CTA 128x128, warp 64x32, BK=64, 3-stage, 1 barrier/iter ----
#define GBM 128
#define GBN 128
#define GBK 64
#define GLDH 72                              // padded row: 72 halves = 144B
#define STG_H ((GBM + GBN) * GLDH)           // 18432 halves per stage
#define GEMM_SMEM (3 * STG_H * 2)            // 110592 B; 2 CTAs = 221KB <= 228KB/SM

__device__ __forceinline__ void gemm_core(const __half* __restrict__ Ag,
                                          const __half* __restrict__ Bg,
                                          float* __restrict__ Cg,
                                          int Cld, int Kstride, int Klen) {
    extern __shared__ __align__(16) __half smh[];
    int tid = threadIdx.x;
    int wid = tid >> 5, lane = tid & 31;
    int wm = wid >> 2, wn = wid & 3;         // warp grid 2x4, warp tile 64x32
    int g = lane >> 2, t = lane & 3;
    int nkt = Klen / GBK;

    auto fill = [&](int kt, int slot) {
        __half* st = smh + slot * STG_H;
        const __half* acol = Ag + (size_t)kt * GBK;
        const __half* bcol = Bg + (size_t)kt * GBK;
        #pragma unroll
        for (int i = 0; i < 8; i++) {
            int id = i * 256 + tid;          // 16B chunk id, 0..2047
            int row = id >> 3, q = id & 7;
            const __half* src = (row < GBM)
                ? acol + (size_t)row * Kstride + q * 8
                : bcol + (size_t)(row - GBM) * Kstride + q * 8;
            cp16(st + row * GLDH + q * 8, src);
        }
        asm volatile("cp.async.commit_group;\n" ::: "memory");
    };

    fill(0, 0);
    if (nkt > 1) fill(1, 1);

    float c[4][4][4];
    #pragma unroll
    for (int mi = 0; mi < 4; mi++)
        #pragma unroll
        for (int ni = 0; ni < 4; ni++)
            #pragma unroll
            for (int q = 0; q < 4; q++) c[mi][ni][q] = 0.f;

    unsigned sbase32 = (unsigned)__cvta_generic_to_shared(smh);
    int mat = lane >> 3, r = lane & 7;
    // A frag (x4): mats (m0-7,k0)(m8-15,k0)(m0-7,k8)(m8-15,k8)
    unsigned aoff = (unsigned)((wm * 64 + (mat & 1) * 8 + r) * GLDH + (mat >> 1) * 8);
    // B frag (x4): mats (n0-7,k0)(n0-7,k8)(n8-15,k0)(n8-15,k8)
    unsigned boff = (unsigned)(GBM * GLDH + (wn * 32 + (mat >> 1) * 8 + r) * GLDH + (mat & 1) * 8);

    for (int kt = 0; kt < nkt; kt++) {
        if (kt + 1 < nkt) asm volatile("cp.async.wait_group 1;\n" ::: "memory");
        else              asm volatile("cp.async.wait_group 0;\n" ::: "memory");
        __syncthreads();                     // all warps done with compute(kt-1)
        if (kt + 2 < nkt) fill(kt + 2, (kt + 2) % 3);   // slot (kt-1)%3, freed above
        unsigned stg = sbase32 + (unsigned)((kt % 3) * STG_H) * 2u;
        unsigned abase = stg + aoff * 2u;
        unsigned bbase = stg + boff * 2u;
        #pragma unroll
        for (int s = 0; s < 4; s++) {
            unsigned ka = abase + (unsigned)(s * 16) * 2u;
            unsigned kb = bbase + (unsigned)(s * 16) * 2u;
            unsigned a[4][4], b[4][2];
            #pragma unroll
            for (int mi = 0; mi < 4; mi++)
                LDSM4(a[mi][0], a[mi][1], a[mi][2], a[mi][3],
                      ka + (unsigned)(mi * 16 * GLDH) * 2u);
            #pragma unroll
            for (int j = 0; j < 2; j++)
                LDSM4(b[2 * j][0], b[2 * j][1], b[2 * j + 1][0], b[2 * j + 1][1],
                      kb + (unsigned)(j * 16 * GLDH) * 2u);
            #pragma unroll
            for (int mi = 0; mi < 4; mi++)
                #pragma unroll
                for (int ni = 0; ni < 4; ni++)
                    MMA_F16(c[mi][ni], a[mi], b[ni]);
        }
    }

    #pragma unroll
    for (int mi = 0; mi < 4; mi++) {
        int r0 = wm * 64 + mi * 16 + g;
        #pragma unroll
        for (int ni = 0; ni < 4; ni++) {
            int cc = wn * 32 + ni * 8 + 2 * t;
            *(float2*)(Cg + (size_t)r0 * Cld + cc) = make_float2(c[mi][ni][0], c[mi][ni][1]);
            *(float2*)(Cg + (size_t)(r0 + 8) * Cld + cc) = make_float2(c[mi][ni][2], c[mi][ni][3]);
        }
    }
}

// launch1: x @ {W1(44 tiles), W3(44), A1(1), A3(1)}^T.  grid (8, 90)
__global__ __launch_bounds__(256, 2) void gemm_fused1_kernel() {
    int bm = blockIdx.x, by = blockIdx.y;
    const __half* Ag = g_xh + (size_t)bm * GBM * DIM;
    const __half* Bg;
    float* Cg;
    int Cld;
    if (by < 44) {
        Bg = g_W1h + (size_t)by * GBN * DIM;
        Cg = g_Y1 + (size_t)bm * GBM * FDIM + by * GBN;
        Cld = FDIM;
    } else if (by < 88) {
        int b = by - 44;
        Bg = g_W3h + (size_t)b * GBN * DIM;
        Cg = g_Y3 + (size_t)bm * GBM * FDIM + b * GBN;
        Cld = FDIM;
    } else if (by == 88) {
        Bg = g_A1h;
        Cg = g_l1 + (size_t)bm * GBM * 128;
        Cld = 128;
    } else {
        Bg = g_A3h;
        Cg = g_l3 + (size_t)bm * GBM * 128;
        Cld = 128;
    }
    gemm_core(Ag, Bg, Cg, Cld, DIM, DIM);
}

// launch2: smix @ W2^T, split-K=2.  grid (8, 16, 2), K=2816 each — 256 CTAs
__global__ __launch_bounds__(256, 2) void gemm_w2_kernel() {
    int bm = blockIdx.x, bn = blockIdx.y, ks = blockIdx.z;
    const __half* Ag = g_smixh + (size_t)bm * GBM * FDIM + ks * 2816;
    const __half* Bg = g_W2h + (size_t)bn * GBN * FDIM + ks * 2816;
    float* Cg = g_psum + (size_t)ks * N_TOK * DIM + (size_t)bm * GBM * DIM + bn * GBN;
    gemm_core(Ag, Bg, Cg, DIM, FDIM, 2816);
}

// ---------------- fp32 -> fp16 conversion ----------------
__global__ void to_half_kernel(const float4* __restrict__ src, __half* __restrict__ dst, int n4) {
    int i = blockIdx.x * blockDim.x + threadIdx.x;
    if (i >= n4) return;
    float4 v = src[i];
    __half2* d = (__half2*)(dst + (size_t)i * 4);
    d[0] = __floats2half2_rn(v.x, v.y);
    d[1] = __floats2half2_rn(v.z, v.w);
}

// combined x + A1 + A3 conversion (keeps gemm_fused1 as the 4th launch)
__global__ void to_half_xa13_kernel(const float4* __restrict__ x,
                                    const float4* __restrict__ a1,
                                    const float4* __restrict__ a3) {
    const int NX4 = N_TOK * DIM / 4;
    const int NA4 = 128 * DIM / 4;
    int i = blockIdx.x * blockDim.x + threadIdx.x;
    const float4* s;
    __half* d;
    int j;
    if (i < NX4)            { s = x;  d = g_xh;  j = i; }
    else if (i < NX4 + NA4) { s = a1; d = g_A1h; j = i - NX4; }
    else if (i < NX4 + 2 * NA4) { s = a3; d = g_A3h; j = i - NX4 - NA4; }
    else return;
    float4 v = s[j];
    __half2* dd = (__half2*)(d + (size_t)j * 4);
    dd[0] = __floats2half2_rn(v.x, v.y);
    dd[1] = __floats2half2_rn(v.z, v.w);
}

__global__ void zero_kernel() {
    int i = blockIdx.x * blockDim.x + threadIdx.x;
    if (i < 2 * N_TOK * RANK) g_l2acc[i] = 0.f;
    if (i < NEXP) g_cnt[i] = 0;
}

// ---------------- router ----------------
__global__ __launch_bounds__(256) void router_kernel(const float* __restrict__ x,
                                                     const float* __restrict__ gate,
                                                     float* __restrict__ logits_out) {
    int n = blockIdx.x;
    __shared__ float xs[DIM];
    __shared__ float lg[NEXP];
    for (int i = threadIdx.x; i < DIM; i += 256) xs[i] = x[(size_t)n * DIM + i];
    __syncthreads();
    int wid = threadIdx.x >> 5, lane = threadIdx.x & 31;
    const float* g = gate + (size_t)wid * DIM;
    float s = 0.f;
    for (int d = lane; d < DIM; d += 32) s += xs[d] * g[d];
    #pragma unroll
    for (int o = 16; o; o >>= 1) s += __shfl_xor_sync(0xffffffffu, s, o);
    if (lane == 0) lg[wid] = s;
    __syncthreads();
    if (threadIdx.x == 0) {
        #pragma unroll
        for (int e = 0; e < NEXP; e++) logits_out[n * NEXP + e] = lg[e];
        int i0 = 0; float v0 = lg[0];
        #pragma unroll
        for (int e = 1; e < NEXP; e++) if (lg[e] > v0) { v0 = lg[e]; i0 = e; }
        int i1 = -1; float v1 = -1e30f;
        #pragma unroll
        for (int e = 0; e < NEXP; e++) if (e != i0 && lg[e] > v1) { v1 = lg[e]; i1 = e; }
        float w0 = 1.f / (1.f + expf(v1 - v0));
        g_topi[2 * n] = i0; g_topi[2 * n + 1] = i1;
        g_topw[2 * n] = w0; g_topw[2 * n + 1] = 1.f - w0;
    }
}

__global__ void build_lists_kernel() {
    int n = blockIdx.x * blockDim.x + threadIdx.x;
    if (n >= N_TOK) return;
    #pragma unroll
    for (int k = 0; k < 2; k++) {
        int e = g_topi[2 * n + k];
        int p = atomicAdd(&g_cnt[e], 1);
        g_list[e * N_TOK + p] = (n << 1) | k;
    }
}

// ---- fused LoRA-B + SwiGLU, token-sliced, prefetched; writes w_k * s (fp16) ----
__global__ __launch_bounds__(128) void expert_kernel(const float* __restrict__ B1,
                                                     const float* __restrict__ B3) {
    int e = blockIdx.y;
    int f0 = blockIdx.x * 128;
    int z = blockIdx.z;                      // token-group slice 0..3
    int f = threadIdx.x;
    __shared__ float B1s[16][128];
    __shared__ float B3s[16][128];
    __shared__ float lv[8][32];
    __shared__ int scode[8];
    {
        const float4* p1 = (const float4*)(B1 + (size_t)(e * FDIM + f0 + f) * RANK);
        const float4* p3 = (const float4*)(B3 + (size_t)(e * FDIM + f0 + f) * RANK);
        #pragma unroll
        for (int q = 0; q < 4; q++) {
            float4 v = p1[q];
            B1s[q * 4 + 0][f] = v.x; B1s[q * 4 + 1][f] = v.y;
            B1s[q * 4 + 2][f] = v.z; B1s[q * 4 + 3][f] = v.w;
            float4 u = p3[q];
            B3s[q * 4 + 0][f] = u.x; B3s[q * 4 + 1][f] = u.y;
            B3s[q * 4 + 2][f] = u.z; B3s[q * 4 + 3][f] = u.w;
        }
    }
    int cnt = g_cnt[e];
    for (int t0 = z * 8; t0 < cnt; t0 += 32) {
        int nt = (cnt - t0 < 8) ? (cnt - t0) : 8;
        __syncthreads();                     // protects B-tiles (1st iter) + lv reuse
        for (int idx = threadIdx.x; idx < nt * 32; idx += 128) {
            int ti = idx >> 5, r = idx & 31;
            int code = g_list[e * N_TOK + t0 + ti];
            int n = code >> 1;
            lv[ti][r] = (r < 16) ? g_l1[n * 128 + e * 16 + r]
                                 : g_l3[n * 128 + e * 16 + (r - 16)];
            if (r == 0) scode[ti] = code;
        }
        __syncthreads();
        // batch-prefetch Y rows + weights (high MLP)
        float yb1[8], yb3[8], wv[8];
        int cd[8];
        for (int ti = 0; ti < nt; ti++) {
            cd[ti] = scode[ti];
            int n = cd[ti] >> 1;
            yb1[ti] = g_Y1[(size_t)n * FDIM + f0 + f];
            yb3[ti] = g_Y3[(size_t)n * FDIM + f0 + f];
            wv[ti] = g_topw[cd[ti]];
        }
        for (int ti = 0; ti < nt; ti++) {
            float h1 = 0.f, h3 = 0.f;
            #pragma unroll
            for (int r = 0; r < 16; r++) {
                h1 += lv[ti][r]      * B1s[r][f];
                h3 += lv[ti][16 + r] * B3s[r][f];
            }
            h1 = yb1[ti] + LSCALE * h1;
            h3 = yb3[ti] + LSCALE * h3;
            float sg = 1.f / (1.f + __expf(-h1));
            g_sbufh[(size_t)cd[ti] * FDIM + f0 + f] = __float2half_rn(wv[ti] * h1 * sg * h3);
        }
    }
}

// ---------------- s_mix = sw0 + sw1 (weights pre-folded), half2 ----------------
__global__ void mix_kernel() {
    int idx = blockIdx.x * blockDim.x + threadIdx.x;   // half2 index
    const int H2 = FDIM / 2;
    if (idx >= N_TOK * H2) return;
    int n = idx / H2;
    int j = idx - n * H2;
    const __half2* s0 = (const __half2*)(g_sbufh + (size_t)(2 * n) * FDIM);
    const __half2* s1 = (const __half2*)(g_sbufh + (size_t)(2 * n + 1) * FDIM);
    float2 a = __half22float2(s0[j]);
    float2 b = __half22float2(s1[j]);
    ((__half2*)(g_smixh + (size_t)n * FDIM))[j] = __floats2half2_rn(a.x + b.x, a.y + b.y);
}

// ---------------- l2acc[code,r] = sum_f sw * A2[e,r,f], token-sliced x8 ----------------
__global__ __launch_bounds__(128) void l2_kernel(const float* __restrict__ A2) {
    int e = blockIdx.y;
    int f0 = blockIdx.x * 512;
    int zslice = blockIdx.z;
    __shared__ float A2s[16][516];
    __shared__ float ss[512];
    for (int r = 0; r < 16; r++)
        for (int c = threadIdx.x; c < 512; c += 128)
            A2s[r][c] = A2[(size_t)(e * 16 + r) * FDIM + f0 + c];
    int rr = threadIdx.x >> 3, jj = threadIdx.x & 7;
    int cnt = g_cnt[e];
    for (int ti = zslice; ti < cnt; ti += 8) {
        int code = g_list[e * N_TOK + ti];
        __syncthreads();
        for (int c = threadIdx.x; c < 512; c += 128)
            ss[c] = __half2float(g_sbufh[(size_t)code * FDIM + f0 + c]);
        __syncthreads();
        float acc = 0.f;
        #pragma unroll 8
        for (int t = 0; t < 64; t++) {
            int c = t * 8 + jj;
            acc += ss[c] * A2s[rr][c];
        }
        acc += __shfl_xor_sync(0xffffffffu, acc, 1);
        acc += __shfl_xor_sync(0xffffffffu, acc, 2);
        acc += __shfl_xor_sync(0xffffffffu, acc, 4);
        if (jj == 0) atomicAdd(&g_l2acc[code * 16 + rr], acc);
    }
}

// ---------------- out = psum0 + psum1 + sum_k LSCALE*(l2 . B2) ----------------
__global__ __launch_bounds__(256) void final_kernel(const float* __restrict__ B2,
                                                    float* __restrict__ out) {
    int n = blockIdx.y;
    int d = blockIdx.x * 256 + threadIdx.x;
    __shared__ float lw[32];
    __shared__ int se[2];
    if (threadIdx.x < 32) {
        lw[threadIdx.x] = g_l2acc[n * 32 + threadIdx.x] * LSCALE;  // w already folded in s
        if (threadIdx.x < 2) se[threadIdx.x] = g_topi[2 * n + threadIdx.x];
    }
    __syncthreads();
    size_t id = (size_t)n * DIM + d;
    float o = g_psum[id] + g_psum[id + (size_t)N_TOK * DIM];
    #pragma unroll
    for (int k = 0; k < 2; k++) {
        const float4* b2 = (const float4*)(B2 + (size_t)(se[k] * DIM + d) * RANK);
        float a = 0.f;
        #pragma unroll
        for (int q = 0; q < 4; q++) {
            float4 v = b2[q];
            a += lw[k * 16 + q * 4 + 0] * v.x + lw[k * 16 + q * 4 + 1] * v.y
               + lw[k * 16 + q * 4 + 2] * v.z + lw[k * 16 + q * 4 + 3] * v.w;
        }
        o += a;
    }
    out[id] = o;
}

// ---------------- host ----------------
extern "C" void kernel_launch(void* const* d_in, const int* in_sizes, int n_in,
                              void* d_out, int out_size) {
    const float* x    = (const float*)d_in[0];
    const float* gate = (const float*)d_in[1];
    const float* W1   = (const float*)d_in[2];
    const float* W3   = (const float*)d_in[3];
    const float* W2   = (const float*)d_in[4];
    const float* A1   = (const float*)d_in[5];
    const float* B1   = (const float*)d_in[6];
    const float* A3   = (const float*)d_in[7];
    const float* B3   = (const float*)d_in[8];
    const float* A2   = (const float*)d_in[9];
    const float* B2   = (const float*)d_in[10];
    float* out = (float*)d_out;
    float* logits = out + (size_t)N_TOK * DIM;   // output order: (out, logits)

    __half *p_W1h, *p_W3h, *p_W2h;
    cudaGetSymbolAddress((void**)&p_W1h, g_W1h);
    cudaGetSymbolAddress((void**)&p_W3h, g_W3h);
    cudaGetSymbolAddress((void**)&p_W2h, g_W2h);

    cudaFuncSetAttribute(gemm_fused1_kernel, cudaFuncAttributeMaxDynamicSharedMemorySize, GEMM_SMEM);
    cudaFuncSetAttribute(gemm_w2_kernel,     cudaFuncAttributeMaxDynamicSharedMemorySize, GEMM_SMEM);

    // launches 1-3 feed gemm_fused1; launch 4 = gemm_fused1 (the profiled one)
    const int NW = FDIM * DIM / 4;
    to_half_kernel<<<(NW + 255) / 256, 256>>>((const float4*)W1, p_W1h, NW);
    to_half_kernel<<<(NW + 255) / 256, 256>>>((const float4*)W3, p_W3h, NW);
    const int NXA = N_TOK * DIM / 4 + 2 * (128 * DIM / 4);
    to_half_xa13_kernel<<<(NXA + 255) / 256, 256>>>((const float4*)x, (const float4*)A1,
                                                    (const float4*)A3);

    gemm_fused1_kernel<<<dim3(8, 90), 256, GEMM_SMEM>>>();

    to_half_kernel<<<(NW + 255) / 256, 256>>>((const float4*)W2, p_W2h, NW);
    zero_kernel<<<128, 256>>>();
    router_kernel<<<N_TOK, 256>>>(x, gate, logits);
    build_lists_kernel<<<4, 256>>>();

    expert_kernel<<<dim3(FDIM / 128, NEXP, 4), 128>>>(B1, B3);
    mix_kernel<<<(N_TOK * FDIM / 2 + 255) / 256, 256>>>();
    l2_kernel<<<dim3(FDIM / 512, NEXP, 8), 128>>>(A2);

    gemm_w2_kernel<<<dim3(8, 16, 2), 256, GEMM_SMEM>>>();
    final_kernel<<<dim3(DIM / 256, N_TOK), 256>>>(B2, out);
}

// round 10
// speedup vs baseline: 4.4988x; 1.0004x over previous
#include <cuda_runtime.h>
#include <cuda_fp16.h>
#include <cstdint>

#define N_TOK 1024
#define DIM   2048
#define FDIM  5632
#define NEXP  8
#define RANK  16
#define LSCALE 2.0f

// ---------------- scratch (device globals; no allocations allowed) ----------------
__device__ __align__(256) __half g_W1h[FDIM * DIM];
__device__ __align__(256) __half g_W3h[FDIM * DIM];
__device__ __align__(256) __half g_W2h[DIM * FDIM];
__device__ __align__(256) __half g_xh[N_TOK * DIM];
__device__ __align__(256) __half g_A1h[128 * DIM];
__device__ __align__(256) __half g_A3h[128 * DIM];
__device__ __align__(256) __half g_smixh[N_TOK * FDIM];
__device__ __align__(256) __half g_sbufh[2 * N_TOK * FDIM];   // holds w_k * s
__device__ __align__(256) __half g_Y1h[N_TOK * FDIM];
__device__ __align__(256) __half g_Y3h[N_TOK * FDIM];
__device__ __align__(256) float g_l1[N_TOK * 128];
__device__ __align__(256) float g_l3[N_TOK * 128];
__device__ __align__(256) float g_psum[2 * N_TOK * DIM];
__device__ __align__(256) float g_l2acc[2 * N_TOK * RANK];
__device__ __align__(256) float g_topw[2 * N_TOK];
__device__ int   g_topi[2 * N_TOK];
__device__ int   g_cnt[NEXP];
__device__ int   g_list[NEXP * N_TOK];

// ---------------- utility ----------------
__device__ __forceinline__ void cp16(const __half* smem_dst, const __half* gsrc) {
    unsigned s = (unsigned)__cvta_generic_to_shared(smem_dst);
    asm volatile("cp.async.cg.shared.global [%0], [%1], 16;\n" :: "r"(s), "l"(gsrc));
}

#define MMA_F16(c, a, b) \
    asm volatile("mma.sync.aligned.m16n8k16.row.col.f32.f16.f16.f32 " \
        "{%0,%1,%2,%3}, {%4,%5,%6,%7}, {%8,%9}, {%0,%1,%2,%3};\n" \
        : "+f"((c)[0]), "+f"((c)[1]), "+f"((c)[2]), "+f"((c)[3]) \
        : "r"((a)[0]), "r"((a)[1]), "r"((a)[2]), "r"((a)[3]), "r"((b)[0]), "r"((b)[1]))

#define LDSM4(r0, r1, r2, r3, addr) \
    asm volatile("ldmatrix.sync.aligned.m8n8.x4.shared.b16 {%0,%1,%2,%3}, [%4];" \
        : "=r"(r0), "=r"(r1), "=r"(r2), "=r"(r3) : "r"(addr))

// ---- fp16 mma GEMM: CTA 128x128, warp 64x32, BK=64, 3-stage, 1 barrier/iter ----
#define GBM 128
#define GBN 128
#define GBK 64
#define GLDH 72                              // padded row: 72 halves = 144B
#define STG_H ((GBM + GBN) * GLDH)           // 18432 halves per stage
#define GEMM_SMEM (3 * STG_H * 2)            // 110592 B; 2 CTAs = 221KB <= 228KB/SM

__device__ __forceinline__ void gemm_core(const __half* __restrict__ Ag,
                                          const __half* __restrict__ Bg,
                                          float* __restrict__ Cg,
                                          __half* __restrict__ Ch,
                                          int Cld, int Kstride, int Klen) {
    extern __shared__ __align__(16) __half smh[];
    int tid = threadIdx.x;
    int wid = tid >> 5, lane = tid & 31;
    int wm = wid >> 2, wn = wid & 3;         // warp grid 2x4, warp tile 64x32
    int g = lane >> 2, t = lane & 3;
    int nkt = Klen / GBK;

    auto fill = [&](int kt, int slot) {
        __half* st = smh + slot * STG_H;
        const __half* acol = Ag + (size_t)kt * GBK;
        const __half* bcol = Bg + (size_t)kt * GBK;
        #pragma unroll
        for (int i = 0; i < 8; i++) {
            int id = i * 256 + tid;          // 16B chunk id, 0..2047
            int row = id >> 3, q = id & 7;
            const __half* src = (row < GBM)
                ? acol + (size_t)row * Kstride + q * 8
                : bcol + (size_t)(row - GBM) * Kstride + q * 8;
            cp16(st + row * GLDH + q * 8, src);
        }
        asm volatile("cp.async.commit_group;\n" ::: "memory");
    };

    fill(0, 0);
    if (nkt > 1) fill(1, 1);

    float c[4][4][4];
    #pragma unroll
    for (int mi = 0; mi < 4; mi++)
        #pragma unroll
        for (int ni = 0; ni < 4; ni++)
            #pragma unroll
            for (int q = 0; q < 4; q++) c[mi][ni][q] = 0.f;

    unsigned sbase32 = (unsigned)__cvta_generic_to_shared(smh);
    int mat = lane >> 3, r = lane & 7;
    unsigned aoff = (unsigned)((wm * 64 + (mat & 1) * 8 + r) * GLDH + (mat >> 1) * 8);
    unsigned boff = (unsigned)(GBM * GLDH + (wn * 32 + (mat >> 1) * 8 + r) * GLDH + (mat & 1) * 8);

    for (int kt = 0; kt < nkt; kt++) {
        if (kt + 1 < nkt) asm volatile("cp.async.wait_group 1;\n" ::: "memory");
        else              asm volatile("cp.async.wait_group 0;\n" ::: "memory");
        __syncthreads();                     // all warps done with compute(kt-1)
        if (kt + 2 < nkt) fill(kt + 2, (kt + 2) % 3);
        unsigned stg = sbase32 + (unsigned)((kt % 3) * STG_H) * 2u;
        unsigned abase = stg + aoff * 2u;
        unsigned bbase = stg + boff * 2u;
        #pragma unroll
        for (int s = 0; s < 4; s++) {
            unsigned ka = abase + (unsigned)(s * 16) * 2u;
            unsigned kb = bbase + (unsigned)(s * 16) * 2u;
            unsigned a[4][4], b[4][2];
            #pragma unroll
            for (int mi = 0; mi < 4; mi++)
                LDSM4(a[mi][0], a[mi][1], a[mi][2], a[mi][3],
                      ka + (unsigned)(mi * 16 * GLDH) * 2u);
            #pragma unroll
            for (int j = 0; j < 2; j++)
                LDSM4(b[2 * j][0], b[2 * j][1], b[2 * j + 1][0], b[2 * j + 1][1],
                      kb + (unsigned)(j * 16 * GLDH) * 2u);
            #pragma unroll
            for (int mi = 0; mi < 4; mi++)
                #pragma unroll
                for (int ni = 0; ni < 4; ni++)
                    MMA_F16(c[mi][ni], a[mi], b[ni]);
        }
    }

    if (Ch) {
        #pragma unroll
        for (int mi = 0; mi < 4; mi++) {
            int r0 = wm * 64 + mi * 16 + g;
            #pragma unroll
            for (int ni = 0; ni < 4; ni++) {
                int cc = wn * 32 + ni * 8 + 2 * t;
                *(__half2*)(Ch + (size_t)r0 * Cld + cc) = __floats2half2_rn(c[mi][ni][0], c[mi][ni][1]);
                *(__half2*)(Ch + (size_t)(r0 + 8) * Cld + cc) = __floats2half2_rn(c[mi][ni][2], c[mi][ni][3]);
            }
        }
    } else {
        #pragma unroll
        for (int mi = 0; mi < 4; mi++) {
            int r0 = wm * 64 + mi * 16 + g;
            #pragma unroll
            for (int ni = 0; ni < 4; ni++) {
                int cc = wn * 32 + ni * 8 + 2 * t;
                *(float2*)(Cg + (size_t)r0 * Cld + cc) = make_float2(c[mi][ni][0], c[mi][ni][1]);
                *(float2*)(Cg + (size_t)(r0 + 8) * Cld + cc) = make_float2(c[mi][ni][2], c[mi][ni][3]);
            }
        }
    }
}

// launch: x @ {W1(44 tiles), W3(44), A1(1), A3(1)}^T.  grid (8, 90)
__global__ __launch_bounds__(256, 2) void gemm_fused1_kernel() {
    int bm = blockIdx.x, by = blockIdx.y;
    const __half* Ag = g_xh + (size_t)bm * GBM * DIM;
    const __half* Bg;
    float* Cg = nullptr;
    __half* Ch = nullptr;
    int Cld;
    if (by < 44) {
        Bg = g_W1h + (size_t)by * GBN * DIM;
        Ch = g_Y1h + (size_t)bm * GBM * FDIM + by * GBN;
        Cld = FDIM;
    } else if (by < 88) {
        int b = by - 44;
        Bg = g_W3h + (size_t)b * GBN * DIM;
        Ch = g_Y3h + (size_t)bm * GBM * FDIM + b * GBN;
        Cld = FDIM;
    } else if (by == 88) {
        Bg = g_A1h;
        Cg = g_l1 + (size_t)bm * GBM * 128;
        Cld = 128;
    } else {
        Bg = g_A3h;
        Cg = g_l3 + (size_t)bm * GBM * 128;
        Cld = 128;
    }
    gemm_core(Ag, Bg, Cg, Ch, Cld, DIM, DIM);
}

// smix @ W2^T, split-K=2.  grid (8, 16, 2), K=2816 each
__global__ __launch_bounds__(256, 2) void gemm_w2_kernel() {
    int bm = blockIdx.x, bn = blockIdx.y, ks = blockIdx.z;
    const __half* Ag = g_smixh + (size_t)bm * GBM * FDIM + ks * 2816;
    const __half* Bg = g_W2h + (size_t)bn * GBN * FDIM + ks * 2816;
    float* Cg = g_psum + (size_t)ks * N_TOK * DIM + (size_t)bm * GBM * DIM + bn * GBN;
    gemm_core(Ag, Bg, Cg, nullptr, DIM, FDIM, 2816);
}

// ---------------- fp32 -> fp16 conversion ----------------
__global__ void to_half_kernel(const float4* __restrict__ src, __half* __restrict__ dst, int n4) {
    int i = blockIdx.x * blockDim.x + threadIdx.x;
    if (i >= n4) return;
    float4 v = src[i];
    __half2* d = (__half2*)(dst + (size_t)i * 4);
    d[0] = __floats2half2_rn(v.x, v.y);
    d[1] = __floats2half2_rn(v.z, v.w);
}

// combined x + A1 + A3 conversion
__global__ void to_half_xa13_kernel(const float4* __restrict__ x,
                                    const float4* __restrict__ a1,
                                    const float4* __restrict__ a3) {
    const int NX4 = N_TOK * DIM / 4;
    const int NA4 = 128 * DIM / 4;
    int i = blockIdx.x * blockDim.x + threadIdx.x;
    const float4* s;
    __half* d;
    int j;
    if (i < NX4)            { s = x;  d = g_xh;  j = i; }
    else if (i < NX4 + NA4) { s = a1; d = g_A1h; j = i - NX4; }
    else if (i < NX4 + 2 * NA4) { s = a3; d = g_A3h; j = i - NX4 - NA4; }
    else return;
    float4 v = s[j];
    __half2* dd = (__half2*)(d + (size_t)j * 4);
    dd[0] = __floats2half2_rn(v.x, v.y);
    dd[1] = __floats2half2_rn(v.z, v.w);
}

__global__ void zero_kernel() {
    int i = blockIdx.x * blockDim.x + threadIdx.x;
    if (i < 2 * N_TOK * RANK) g_l2acc[i] = 0.f;
    if (i < NEXP) g_cnt[i] = 0;
}

// ---------------- router ----------------
__global__ __launch_bounds__(256) void router_kernel(const float* __restrict__ x,
                                                     const float* __restrict__ gate,
                                                     float* __restrict__ logits_out) {
    int n = blockIdx.x;
    __shared__ float xs[DIM];
    __shared__ float lg[NEXP];
    for (int i = threadIdx.x; i < DIM; i += 256) xs[i] = x[(size_t)n * DIM + i];
    __syncthreads();
    int wid = threadIdx.x >> 5, lane = threadIdx.x & 31;
    const float* g = gate + (size_t)wid * DIM;
    float s = 0.f;
    for (int d = lane; d < DIM; d += 32) s += xs[d] * g[d];
    #pragma unroll
    for (int o = 16; o; o >>= 1) s += __shfl_xor_sync(0xffffffffu, s, o);
    if (lane == 0) lg[wid] = s;
    __syncthreads();
    if (threadIdx.x == 0) {
        #pragma unroll
        for (int e = 0; e < NEXP; e++) logits_out[n * NEXP + e] = lg[e];
        int i0 = 0; float v0 = lg[0];
        #pragma unroll
        for (int e = 1; e < NEXP; e++) if (lg[e] > v0) { v0 = lg[e]; i0 = e; }
        int i1 = -1; float v1 = -1e30f;
        #pragma unroll
        for (int e = 0; e < NEXP; e++) if (e != i0 && lg[e] > v1) { v1 = lg[e]; i1 = e; }
        float w0 = 1.f / (1.f + expf(v1 - v0));
        g_topi[2 * n] = i0; g_topi[2 * n + 1] = i1;
        g_topw[2 * n] = w0; g_topw[2 * n + 1] = 1.f - w0;
    }
}

__global__ void build_lists_kernel() {
    int n = blockIdx.x * blockDim.x + threadIdx.x;
    if (n >= N_TOK) return;
    #pragma unroll
    for (int k = 0; k < 2; k++) {
        int e = g_topi[2 * n + k];
        int p = atomicAdd(&g_cnt[e], 1);
        g_list[e * N_TOK + p] = (n << 1) | k;
    }
}

// ---- fused LoRA-B + SwiGLU, token-sliced, prefetched; writes w_k * s (fp16) ----
__global__ __launch_bounds__(128) void expert_kernel(const float* __restrict__ B1,
                                                     const float* __restrict__ B3) {
    int e = blockIdx.y;
    int f0 = blockIdx.x * 128;
    int z = blockIdx.z;                      // token-group slice 0..3
    int f = threadIdx.x;
    __shared__ float B1s[16][128];
    __shared__ float B3s[16][128];
    __shared__ float lv[8][32];
    __shared__ int scode[8];
    {
        const float4* p1 = (const float4*)(B1 + (size_t)(e * FDIM + f0 + f) * RANK);
        const float4* p3 = (const float4*)(B3 + (size_t)(e * FDIM + f0 + f) * RANK);
        #pragma unroll
        for (int q = 0; q < 4; q++) {
            float4 v = p1[q];
            B1s[q * 4 + 0][f] = v.x; B1s[q * 4 + 1][f] = v.y;
            B1s[q * 4 + 2][f] = v.z; B1s[q * 4 + 3][f] = v.w;
            float4 u = p3[q];
            B3s[q * 4 + 0][f] = u.x; B3s[q * 4 + 1][f] = u.y;
            B3s[q * 4 + 2][f] = u.z; B3s[q * 4 + 3][f] = u.w;
        }
    }
    int cnt = g_cnt[e];
    for (int t0 = z * 8; t0 < cnt; t0 += 32) {
        int nt = (cnt - t0 < 8) ? (cnt - t0) : 8;
        __syncthreads();                     // protects B-tiles (1st iter) + lv reuse
        for (int idx = threadIdx.x; idx < nt * 32; idx += 128) {
            int ti = idx >> 5, r = idx & 31;
            int code = g_list[e * N_TOK + t0 + ti];
            int n = code >> 1;
            lv[ti][r] = (r < 16) ? g_l1[n * 128 + e * 16 + r]
                                 : g_l3[n * 128 + e * 16 + (r - 16)];
            if (r == 0) scode[ti] = code;
        }
        __syncthreads();
        // batch-prefetch Y rows + weights (high MLP)
        float yb1[8], yb3[8], wv[8];
        int cd[8];
        for (int ti = 0; ti < nt; ti++) {
            cd[ti] = scode[ti];
            int n = cd[ti] >> 1;
            yb1[ti] = __half2float(g_Y1h[(size_t)n * FDIM + f0 + f]);
            yb3[ti] = __half2float(g_Y3h[(size_t)n * FDIM + f0 + f]);
            wv[ti] = g_topw[cd[ti]];
        }
        for (int ti = 0; ti < nt; ti++) {
            float h1 = 0.f, h3 = 0.f;
            #pragma unroll
            for (int r = 0; r < 16; r++) {
                h1 += lv[ti][r]      * B1s[r][f];
                h3 += lv[ti][16 + r] * B3s[r][f];
            }
            h1 = yb1[ti] + LSCALE * h1;
            h3 = yb3[ti] + LSCALE * h3;
            float sg = 1.f / (1.f + __expf(-h1));
            g_sbufh[(size_t)cd[ti] * FDIM + f0 + f] = __float2half_rn(wv[ti] * h1 * sg * h3);
        }
    }
}

// ---------------- s_mix = sw0 + sw1 (weights pre-folded), half2 ----------------
__global__ void mix_kernel() {
    int idx = blockIdx.x * blockDim.x + threadIdx.x;   // half2 index
    const int H2 = FDIM / 2;
    if (idx >= N_TOK * H2) return;
    int n = idx / H2;
    int j = idx - n * H2;
    const __half2* s0 = (const __half2*)(g_sbufh + (size_t)(2 * n) * FDIM);
    const __half2* s1 = (const __half2*)(g_sbufh + (size_t)(2 * n + 1) * FDIM);
    float2 a = __half22float2(s0[j]);
    float2 b = __half22float2(s1[j]);
    ((__half2*)(g_smixh + (size_t)n * FDIM))[j] = __floats2half2_rn(a.x + b.x, a.y + b.y);
}

// ---------------- l2acc[code,r] = sum_f sw * A2[e,r,f], token-sliced x8 ----------------
__global__ __launch_bounds__(128) void l2_kernel(const float* __restrict__ A2) {
    int e = blockIdx.y;
    int f0 = blockIdx.x * 512;
    int zslice = blockIdx.z;
    __shared__ float A2s[16][516];
    __shared__ float ss[512];
    for (int r = 0; r < 16; r++)
        for (int c = threadIdx.x; c < 512; c += 128)
            A2s[r][c] = A2[(size_t)(e * 16 + r) * FDIM + f0 + c];
    int rr = threadIdx.x >> 3, jj = threadIdx.x & 7;
    int cnt = g_cnt[e];
    for (int ti = zslice; ti < cnt; ti += 8) {
        int code = g_list[e * N_TOK + ti];
        __syncthreads();
        for (int c = threadIdx.x; c < 512; c += 128)
            ss[c] = __half2float(g_sbufh[(size_t)code * FDIM + f0 + c]);
        __syncthreads();
        float acc = 0.f;
        #pragma unroll 8
        for (int t = 0; t < 64; t++) {
            int c = t * 8 + jj;
            acc += ss[c] * A2s[rr][c];
        }
        acc += __shfl_xor_sync(0xffffffffu, acc, 1);
        acc += __shfl_xor_sync(0xffffffffu, acc, 2);
        acc += __shfl_xor_sync(0xffffffffu, acc, 4);
        if (jj == 0) atomicAdd(&g_l2acc[code * 16 + rr], acc);
    }
}

// ---------------- out = psum0 + psum1 + sum_k LSCALE*(l2 . B2) ----------------
__global__ __launch_bounds__(256) void final_kernel(const float* __restrict__ B2,
                                                    float* __restrict__ out) {
    int n = blockIdx.y;
    int d = blockIdx.x * 256 + threadIdx.x;
    __shared__ float lw[32];
    __shared__ int se[2];
    if (threadIdx.x < 32) {
        lw[threadIdx.x] = g_l2acc[n * 32 + threadIdx.x] * LSCALE;
        if (threadIdx.x < 2) se[threadIdx.x] = g_topi[2 * n + threadIdx.x];
    }
    __syncthreads();
    size_t id = (size_t)n * DIM + d;
    float o = g_psum[id] + g_psum[id + (size_t)N_TOK * DIM];
    #pragma unroll
    for (int k = 0; k < 2; k++) {
        const float4* b2 = (const float4*)(B2 + (size_t)(se[k] * DIM + d) * RANK);
        float a = 0.f;
        #pragma unroll
        for (int q = 0; q < 4; q++) {
            float4 v = b2[q];
            a += lw[k * 16 + q * 4 + 0] * v.x + lw[k * 16 + q * 4 + 1] * v.y
               + lw[k * 16 + q * 4 + 2] * v.z + lw[k * 16 + q * 4 + 3] * v.w;
        }
        o += a;
    }
    out[id] = o;
}

// ---------------- static streams/events (created at program load, before harness) ----
static cudaStream_t g_s2, g_s3;
static cudaEvent_t g_ev0, g_ev2, g_ev3, g_evE, g_ev5;
static bool g_stream_init = []() {
    cudaStreamCreateWithFlags(&g_s2, cudaStreamNonBlocking);
    cudaStreamCreateWithFlags(&g_s3, cudaStreamNonBlocking);
    cudaEventCreateWithFlags(&g_ev0, cudaEventDisableTiming);
    cudaEventCreateWithFlags(&g_ev2, cudaEventDisableTiming);
    cudaEventCreateWithFlags(&g_ev3, cudaEventDisableTiming);
    cudaEventCreateWithFlags(&g_evE, cudaEventDisableTiming);
    cudaEventCreateWithFlags(&g_ev5, cudaEventDisableTiming);
    return true;
}();

// ---------------- host ----------------
extern "C" void kernel_launch(void* const* d_in, const int* in_sizes, int n_in,
                              void* d_out, int out_size) {
    const float* x    = (const float*)d_in[0];
    const float* gate = (const float*)d_in[1];
    const float* W1   = (const float*)d_in[2];
    const float* W3   = (const float*)d_in[3];
    const float* W2   = (const float*)d_in[4];
    const float* A1   = (const float*)d_in[5];
    const float* B1   = (const float*)d_in[6];
    const float* A3   = (const float*)d_in[7];
    const float* B3   = (const float*)d_in[8];
    const float* A2   = (const float*)d_in[9];
    const float* B2   = (const float*)d_in[10];
    float* out = (float*)d_out;
    float* logits = out + (size_t)N_TOK * DIM;   // output order: (out, logits)

    __half *p_W1h, *p_W3h, *p_W2h;
    cudaGetSymbolAddress((void**)&p_W1h, g_W1h);
    cudaGetSymbolAddress((void**)&p_W3h, g_W3h);
    cudaGetSymbolAddress((void**)&p_W2h, g_W2h);

    cudaFuncSetAttribute(gemm_fused1_kernel, cudaFuncAttributeMaxDynamicSharedMemorySize, GEMM_SMEM);
    cudaFuncSetAttribute(gemm_w2_kernel,     cudaFuncAttributeMaxDynamicSharedMemorySize, GEMM_SMEM);

    const int NW = FDIM * DIM / 4;
    const int NXA = N_TOK * DIM / 4 + 2 * (128 * DIM / 4);

    // fork point
    cudaEventRecord(g_ev0, 0);

    // main stream: W1 convert, x/A1/A3 convert, then gemm1 (launch #4 for ncu)
    to_half_kernel<<<(NW + 255) / 256, 256>>>((const float4*)W1, p_W1h, NW);
    to_half_xa13_kernel<<<(NXA + 255) / 256, 256>>>((const float4*)x, (const float4*)A1,
                                                    (const float4*)A3);
    // s3: W3 convert in parallel
    cudaStreamWaitEvent(g_s3, g_ev0, 0);
    to_half_kernel<<<(NW + 255) / 256, 256, 0, g_s3>>>((const float4*)W3, p_W3h, NW);
    cudaEventRecord(g_ev3, g_s3);

    cudaStreamWaitEvent(0, g_ev3, 0);
    gemm_fused1_kernel<<<dim3(8, 90), 256, GEMM_SMEM>>>();

    // s2: independent chain (W2 convert, zero, router, build) overlaps gemm1
    cudaStreamWaitEvent(g_s2, g_ev0, 0);
    to_half_kernel<<<(NW + 255) / 256, 256, 0, g_s2>>>((const float4*)W2, p_W2h, NW);
    zero_kernel<<<128, 256, 0, g_s2>>>();
    router_kernel<<<N_TOK, 256, 0, g_s2>>>(x, gate, logits);
    build_lists_kernel<<<4, 256, 0, g_s2>>>();
    cudaEventRecord(g_ev2, g_s2);

    // expert needs gemm1 (main) + router/build (ev2)
    cudaStreamWaitEvent(0, g_ev2, 0);
    expert_kernel<<<dim3(FDIM / 128, NEXP, 4), 128>>>(B1, B3);
    cudaEventRecord(g_evE, 0);

    // l2 on s3 in parallel with mix + gemm_w2 on main
    cudaStreamWaitEvent(g_s3, g_evE, 0);
    l2_kernel<<<dim3(FDIM / 512, NEXP, 8), 128, 0, g_s3>>>(A2);
    cudaEventRecord(g_ev5, g_s3);

    mix_kernel<<<(N_TOK * FDIM / 2 + 255) / 256, 256>>>();
    gemm_w2_kernel<<<dim3(8, 16, 2), 256, GEMM_SMEM>>>();

    cudaStreamWaitEvent(0, g_ev5, 0);
    final_kernel<<<dim3(DIM / 256, N_TOK), 256>>>(B2, out);
}